// round 2
// baseline (speedup 1.0000x reference)
#include <cuda_runtime.h>
#include <math.h>

#define BB 2
#define CC 512
#define PP 4096
#define NHEAD 8
#define GG 32
#define CPG 16
#define EPSV 1e-5f

// scratch (device globals: allocation-free per harness rules)
__device__ float g_h[BB * CC * PP];        // groupnorm output        (16 MB)
__device__ float g_qkv[BB * 3 * CC * PP];  // qkv projections         (50 MB)
__device__ float g_att[BB * CC * PP];      // attention output        (16 MB)

// ---------------------------------------------------------------------------
// GroupNorm: one block per (batch, group). 16 channels x 4096 = 65536 elems.
// ---------------------------------------------------------------------------
__global__ __launch_bounds__(256) void gn_kernel(const float* __restrict__ x,
                                                 const float* __restrict__ gw,
                                                 const float* __restrict__ gb,
                                                 float* __restrict__ out) {
    int bg = blockIdx.x;
    int b = bg / GG, g = bg % GG;
    const float4* xp = (const float4*)(x + ((size_t)b * CC + g * CPG) * PP);
    float4* op = (float4*)(out + ((size_t)b * CC + g * CPG) * PP);
    const int N4 = CPG * PP / 4;  // 16384
    float s = 0.f, s2 = 0.f;
    for (int i = threadIdx.x; i < N4; i += 256) {
        float4 v = xp[i];
        s += v.x + v.y + v.z + v.w;
        s2 += v.x * v.x + v.y * v.y + v.z * v.z + v.w * v.w;
    }
    __shared__ float rs[256], rs2[256];
    rs[threadIdx.x] = s; rs2[threadIdx.x] = s2;
    __syncthreads();
    for (int o = 128; o > 0; o >>= 1) {
        if (threadIdx.x < o) { rs[threadIdx.x] += rs[threadIdx.x + o]; rs2[threadIdx.x] += rs2[threadIdx.x + o]; }
        __syncthreads();
    }
    __shared__ float smean, srstd;
    if (threadIdx.x == 0) {
        float mean = rs[0] / (float)(CPG * PP);
        float var = rs2[0] / (float)(CPG * PP) - mean * mean;
        smean = mean;
        srstd = rsqrtf(var + EPSV);
    }
    __syncthreads();
    float mean = smean, rstd = srstd;
    for (int i = threadIdx.x; i < N4; i += 256) {
        int c = g * CPG + (i >> 10);   // (i*4)/4096
        float ga = gw[c] * rstd, be = gb[c];
        float4 v = xp[i];
        v.x = (v.x - mean) * ga + be;
        v.y = (v.y - mean) * ga + be;
        v.z = (v.z - mean) * ga + be;
        v.w = (v.w - mean) * ga + be;
        op[i] = v;
    }
}

// ---------------------------------------------------------------------------
// Generic channel GEMM: Out[b][o][p] = sum_c W[o][c] * In[b][c][p]
//                        (+ bias[o] + resid[b][o][p] when provided)
// 64x64 output tile per block, K-tile 16, 256 threads, 4x4 micro-tile.
// ---------------------------------------------------------------------------
__global__ __launch_bounds__(256) void gemm64(const float* __restrict__ W,
                                              const float* __restrict__ In,
                                              float* __restrict__ Out,
                                              const float* __restrict__ bias,
                                              const float* __restrict__ resid,
                                              int Mrows) {
    __shared__ float Ws[16][64];
    __shared__ float Hs[16][64];
    int tid = threadIdx.x;
    int b = blockIdx.z;
    int o0 = blockIdx.y << 6, p0 = blockIdx.x << 6;
    const float* Wp = W + (size_t)o0 * CC;
    const float* Ip = In + (size_t)b * CC * PP + p0;
    int ty = tid >> 4, tx = tid & 15;
    int wrow = tid >> 2, wq = (tid & 3) << 2;
    int hk = tid >> 4, hq = (tid & 15) << 2;
    float acc[4][4] = {};
    for (int k0 = 0; k0 < CC; k0 += 16) {
        __syncthreads();
        float4 w4 = *(const float4*)(Wp + (size_t)wrow * CC + k0 + wq);
        Ws[wq + 0][wrow] = w4.x;
        Ws[wq + 1][wrow] = w4.y;
        Ws[wq + 2][wrow] = w4.z;
        Ws[wq + 3][wrow] = w4.w;
        *(float4*)&Hs[hk][hq] = *(const float4*)(Ip + (size_t)(k0 + hk) * PP + hq);
        __syncthreads();
#pragma unroll
        for (int kk = 0; kk < 16; kk++) {
            float4 a = *(float4*)&Ws[kk][ty << 2];
            float4 h = *(float4*)&Hs[kk][tx << 2];
            const float* af = (const float*)&a;
            const float* hf = (const float*)&h;
#pragma unroll
            for (int r = 0; r < 4; r++)
#pragma unroll
                for (int u = 0; u < 4; u++) acc[r][u] += af[r] * hf[u];
        }
    }
#pragma unroll
    for (int r = 0; r < 4; r++) {
        int o = o0 + (ty << 2) + r;
        float bv = bias ? bias[o] : 0.f;
        size_t off = ((size_t)b * Mrows + o) * PP + p0 + (tx << 2);
        float4 v = make_float4(acc[r][0] + bv, acc[r][1] + bv, acc[r][2] + bv, acc[r][3] + bv);
        if (resid) {
            float4 rr = *(const float4*)(resid + off);
            v.x += rr.x; v.y += rr.y; v.z += rr.z; v.w += rr.w;
        }
        *(float4*)(Out + off) = v;
    }
}

// ---------------------------------------------------------------------------
// Flash attention. Per block: one (bh, 64-row query tile).
// qkv layout: [b][3C][P]; head nh uses channels [nh*192, nh*192+192):
//   q rows +0..63, k rows +64..127, v rows +128..191.
// Online softmax stats (m, l) live in registers, reduced across the 16 tx
// lanes of each half-warp via shfl (rows are replicated over tx).
// smem: qs(16KB) + kv(16KB, K then V reuse) + ss(16KB) = exactly 48KB static.
// ---------------------------------------------------------------------------
__global__ __launch_bounds__(256) void attn_kernel(const float* __restrict__ qkv,
                                                   float* __restrict__ att) {
    __shared__ float qs[64 * 64];
    __shared__ float kv[64 * 64];
    __shared__ float ss[64 * 64];
    int bh = blockIdx.y;
    int i0 = blockIdx.x << 6;
    int b = bh >> 3, nh = bh & 7;
    const float* qb = qkv + ((size_t)b * 3 * CC + nh * 192) * PP;
    const float* kb = qb + (size_t)64 * PP;
    const float* vb = qb + (size_t)128 * PP;
    int tid = threadIdx.x;
    int ty = tid >> 4, tx = tid & 15;
    const int ii = ty << 2;
    const int jj = tx << 2;

    // load Q tile (scaled by 1/8 = scale^2): qs[c][i]
#pragma unroll
    for (int it = 0; it < 4; it++) {
        int idx = tid + it * 256;
        int c = idx >> 4, q4 = (idx & 15) << 2;
        float4 v = *(const float4*)(qb + (size_t)c * PP + i0 + q4);
        v.x *= 0.125f; v.y *= 0.125f; v.z *= 0.125f; v.w *= 0.125f;
        *(float4*)&qs[c * 64 + q4] = v;
    }

    float O[4][4] = {};
    float mrow[4], lrow[4];
#pragma unroll
    for (int r = 0; r < 4; r++) { mrow[r] = -INFINITY; lrow[r] = 0.f; }

    for (int j0 = 0; j0 < PP; j0 += 64) {
        __syncthreads();  // prev PV done with ss/kv
        // load K tile: kv[c][j]
#pragma unroll
        for (int it = 0; it < 4; it++) {
            int idx = tid + it * 256;
            int c = idx >> 4, q4 = (idx & 15) << 2;
            *(float4*)&kv[c * 64 + q4] = *(const float4*)(kb + (size_t)c * PP + j0 + q4);
        }
        __syncthreads();

        // S = (Q*s)(K*s)^T for this 64x64 tile, 4x4 per thread
        float s[4][4] = {};
#pragma unroll 16
        for (int c = 0; c < 64; c++) {
            float4 a = *(float4*)&qs[c * 64 + ii];
            float4 bk = *(float4*)&kv[c * 64 + jj];
            const float* af = (const float*)&a;
            const float* bf = (const float*)&bk;
#pragma unroll
            for (int r = 0; r < 4; r++)
#pragma unroll
                for (int u = 0; u < 4; u++) s[r][u] += af[r] * bf[u];
        }

        // online softmax: per-row reduce over the 16 tx lanes (half-warp)
#pragma unroll
        for (int r = 0; r < 4; r++) {
            float mx = fmaxf(fmaxf(s[r][0], s[r][1]), fmaxf(s[r][2], s[r][3]));
            mx = fmaxf(mx, __shfl_xor_sync(0xffffffffu, mx, 1));
            mx = fmaxf(mx, __shfl_xor_sync(0xffffffffu, mx, 2));
            mx = fmaxf(mx, __shfl_xor_sync(0xffffffffu, mx, 4));
            mx = fmaxf(mx, __shfl_xor_sync(0xffffffffu, mx, 8));
            float mnew = fmaxf(mrow[r], mx);
            float alpha = __expf(mrow[r] - mnew);
            float sum = 0.f;
#pragma unroll
            for (int u = 0; u < 4; u++) {
                s[r][u] = __expf(s[r][u] - mnew);
                sum += s[r][u];
            }
            sum += __shfl_xor_sync(0xffffffffu, sum, 1);
            sum += __shfl_xor_sync(0xffffffffu, sum, 2);
            sum += __shfl_xor_sync(0xffffffffu, sum, 4);
            sum += __shfl_xor_sync(0xffffffffu, sum, 8);
            lrow[r] = lrow[r] * alpha + sum;
            mrow[r] = mnew;
#pragma unroll
            for (int u = 0; u < 4; u++) O[r][u] *= alpha;
        }
        // write P tile
#pragma unroll
        for (int r = 0; r < 4; r++)
            *(float4*)&ss[(ii + r) * 64 + jj] = make_float4(s[r][0], s[r][1], s[r][2], s[r][3]);
        __syncthreads();  // ss visible; all K reads done -> kv reusable

        // load V tile transposed with float4-granular XOR swizzle:
        //   vs[j][c] stored at  j*64 + ((c/4) ^ (j&15))*4 + (c&3)
#pragma unroll
        for (int it = 0; it < 4; it++) {
            int idx = tid + it * 256;
            int c = idx >> 4, q = (idx & 15) << 2;
            float4 v = *(const float4*)(vb + (size_t)c * PP + j0 + q);
            int c4 = c >> 2, cm = c & 3;
            kv[(q + 0) * 64 + ((c4 ^ ((q + 0) & 15)) << 2) + cm] = v.x;
            kv[(q + 1) * 64 + ((c4 ^ ((q + 1) & 15)) << 2) + cm] = v.y;
            kv[(q + 2) * 64 + ((c4 ^ ((q + 2) & 15)) << 2) + cm] = v.z;
            kv[(q + 3) * 64 + ((c4 ^ ((q + 3) & 15)) << 2) + cm] = v.w;
        }
        __syncthreads();

        // O[i][c] += sum_j P[i][j] * V[c][j]
#pragma unroll 4
        for (int j = 0; j < 64; j += 4) {
            float4 A[4], Bv[4];
#pragma unroll
            for (int r = 0; r < 4; r++) A[r] = *(float4*)&ss[(ii + r) * 64 + j];
#pragma unroll
            for (int t = 0; t < 4; t++)
                Bv[t] = *(float4*)&kv[(j + t) * 64 + ((tx ^ ((j + t) & 15)) << 2)];
            const float* Af = (const float*)A;
            const float* Bf = (const float*)Bv;
#pragma unroll
            for (int t = 0; t < 4; t++)
#pragma unroll
                for (int r = 0; r < 4; r++)
#pragma unroll
                    for (int u = 0; u < 4; u++) O[r][u] += Af[r * 4 + t] * Bf[t * 4 + u];
        }
    }

    // finalize: divide by l, store to att[b][nh*64 + c][i]
#pragma unroll
    for (int r = 0; r < 4; r++) {
        float inv = 1.f / lrow[r];
#pragma unroll
        for (int u = 0; u < 4; u++) O[r][u] *= inv;
    }
    float* ab = att + ((size_t)b * CC + nh * 64) * PP;
#pragma unroll
    for (int u = 0; u < 4; u++) {
        int c = jj + u;
        *(float4*)(ab + (size_t)c * PP + i0 + ii) =
            make_float4(O[0][u], O[1][u], O[2][u], O[3][u]);
    }
}

// ---------------------------------------------------------------------------
extern "C" void kernel_launch(void* const* d_in, const int* in_sizes, int n_in,
                              void* d_out, int out_size) {
    const float* x = (const float*)d_in[0];
    const float* qkv_w = (const float*)d_in[1];
    const float* proj_w = (const float*)d_in[2];
    const float* proj_b = (const float*)d_in[3];
    const float* gn_w = (const float*)d_in[4];
    const float* gn_b = (const float*)d_in[5];
    float* out = (float*)d_out;

    float *hp, *qkvp, *attp;
    cudaGetSymbolAddress((void**)&hp, g_h);
    cudaGetSymbolAddress((void**)&qkvp, g_qkv);
    cudaGetSymbolAddress((void**)&attp, g_att);

    // 1) GroupNorm
    gn_kernel<<<BB * GG, 256>>>(x, gn_w, gn_b, hp);
    // 2) QKV 1x1 conv: [1536x512] @ [512x4096] per batch
    gemm64<<<dim3(PP / 64, (3 * CC) / 64, BB), 256>>>(qkv_w, hp, qkvp, nullptr, nullptr, 3 * CC);
    // 3) flash attention over 16 (b,head) pairs, 64 query tiles each
    attn_kernel<<<dim3(PP / 64, BB * NHEAD), 256>>>(qkvp, attp);
    // 4) proj 1x1 conv + bias + residual
    gemm64<<<dim3(PP / 64, CC / 64, BB), 256>>>(proj_w, attp, out, proj_b, x, CC);
}

// round 4
// speedup vs baseline: 1.9825x; 1.9825x over previous
#include <cuda_runtime.h>
#include <cuda_bf16.h>
#include <mma.h>
#include <math.h>
#include <stdint.h>
using namespace nvcuda;

#define BB 2
#define CC 512
#define PP 4096
#define NBH 16
#define GG 32
#define CPG 16
#define EPSV 1e-5f

__device__ float g_h[BB * CC * PP];
__device__ float g_qkv[BB * 3 * CC * PP];
__device__ float g_att[BB * CC * PP];
__device__ __align__(1024) __nv_bfloat16 g_qhi[NBH * PP * 64];
__device__ __align__(1024) __nv_bfloat16 g_qlo[NBH * PP * 64];
__device__ __align__(1024) __nv_bfloat16 g_khi[NBH * PP * 64];
__device__ __align__(1024) __nv_bfloat16 g_klo[NBH * PP * 64];
__device__ __align__(1024) __nv_bfloat16 g_vhi[NBH * PP * 64];
__device__ __align__(1024) __nv_bfloat16 g_vlo[NBH * PP * 64];

__device__ __forceinline__ uint32_t smem_u32(const void* p) {
    uint32_t a;
    asm("{ .reg .u64 t; cvta.to.shared.u64 t, %1; cvt.u32.u64 %0, t; }" : "=r"(a) : "l"(p));
    return a;
}
__device__ __forceinline__ void cpa16(uint32_t dst, const void* src) {
    asm volatile("cp.async.cg.shared.global [%0], [%1], 16;" :: "r"(dst), "l"(src));
}
#define CPA_COMMIT() asm volatile("cp.async.commit_group;" ::: "memory")
#define CPA_WAIT1()  asm volatile("cp.async.wait_group 1;" ::: "memory")
#define CPA_WAIT0()  asm volatile("cp.async.wait_group 0;" ::: "memory")
__device__ __forceinline__ unsigned short bfu(__nv_bfloat16 x) { return *(unsigned short*)&x; }

// --------------------------- GroupNorm (R1, passing) -----------------------
__global__ __launch_bounds__(256) void gn_kernel(const float* __restrict__ x,
        const float* __restrict__ gw, const float* __restrict__ gb, float* __restrict__ out) {
    int b = blockIdx.x / GG, g = blockIdx.x % GG;
    const float4* xp = (const float4*)(x + ((size_t)b * CC + g * CPG) * PP);
    float4* op = (float4*)(out + ((size_t)b * CC + g * CPG) * PP);
    const int N4 = CPG * PP / 4;
    float s = 0.f, s2 = 0.f;
    for (int i = threadIdx.x; i < N4; i += 256) {
        float4 v = xp[i];
        s += v.x + v.y + v.z + v.w;
        s2 += v.x * v.x + v.y * v.y + v.z * v.z + v.w * v.w;
    }
    __shared__ float rs[256], rs2[256];
    rs[threadIdx.x] = s; rs2[threadIdx.x] = s2;
    __syncthreads();
    for (int o = 128; o > 0; o >>= 1) {
        if (threadIdx.x < o) { rs[threadIdx.x] += rs[threadIdx.x + o]; rs2[threadIdx.x] += rs2[threadIdx.x + o]; }
        __syncthreads();
    }
    __shared__ float sm2[2];
    if (threadIdx.x == 0) {
        float mean = rs[0] / (float)(CPG * PP);
        sm2[0] = mean; sm2[1] = rsqrtf(rs2[0] / (float)(CPG * PP) - mean * mean + EPSV);
    }
    __syncthreads();
    float mean = sm2[0], rstd = sm2[1];
    for (int i = threadIdx.x; i < N4; i += 256) {
        int c = g * CPG + (i >> 10);
        float ga = gw[c] * rstd, be = gb[c];
        float4 v = xp[i];
        v.x = (v.x - mean) * ga + be; v.y = (v.y - mean) * ga + be;
        v.z = (v.z - mean) * ga + be; v.w = (v.w - mean) * ga + be;
        op[i] = v;
    }
}

// ------------------------- SIMT channel GEMM (R1, passing) -----------------
__global__ __launch_bounds__(256) void gemm64(const float* __restrict__ W, const float* __restrict__ In,
        float* __restrict__ Out, const float* __restrict__ bias, const float* __restrict__ resid, int Mrows) {
    __shared__ float Ws[16][64];
    __shared__ float Hs[16][64];
    int tid = threadIdx.x, b = blockIdx.z;
    int o0 = blockIdx.y << 6, p0 = blockIdx.x << 6;
    const float* Wp = W + (size_t)o0 * CC;
    const float* Ip = In + (size_t)b * CC * PP + p0;
    int ty = tid >> 4, tx = tid & 15;
    int wrow = tid >> 2, wq = (tid & 3) << 2;
    int hk = tid >> 4, hq = (tid & 15) << 2;
    float acc[4][4] = {};
    for (int k0 = 0; k0 < CC; k0 += 16) {
        __syncthreads();
        float4 w4 = *(const float4*)(Wp + (size_t)wrow * CC + k0 + wq);
        Ws[wq][wrow] = w4.x; Ws[wq + 1][wrow] = w4.y; Ws[wq + 2][wrow] = w4.z; Ws[wq + 3][wrow] = w4.w;
        *(float4*)&Hs[hk][hq] = *(const float4*)(Ip + (size_t)(k0 + hk) * PP + hq);
        __syncthreads();
#pragma unroll
        for (int kk = 0; kk < 16; kk++) {
            float4 a = *(float4*)&Ws[kk][ty << 2];
            float4 h = *(float4*)&Hs[kk][tx << 2];
            const float *af = (const float*)&a, *hf = (const float*)&h;
#pragma unroll
            for (int r = 0; r < 4; r++)
#pragma unroll
                for (int u = 0; u < 4; u++) acc[r][u] += af[r] * hf[u];
        }
    }
#pragma unroll
    for (int r = 0; r < 4; r++) {
        int o = o0 + (ty << 2) + r;
        float bv = bias ? bias[o] : 0.f;
        size_t off = ((size_t)b * Mrows + o) * PP + p0 + (tx << 2);
        float4 v = make_float4(acc[r][0] + bv, acc[r][1] + bv, acc[r][2] + bv, acc[r][3] + bv);
        if (resid) { float4 rr = *(const float4*)(resid + off); v.x += rr.x; v.y += rr.y; v.z += rr.z; v.w += rr.w; }
        *(float4*)(Out + off) = v;
    }
}

// ---- prep: transpose q,k,v to [token][64] bf16 hi/lo; q scaled by 1/8 -----
__global__ __launch_bounds__(256) void prep_kernel(const float* __restrict__ qkv) {
    __shared__ float ts[64][65];
    int bh = blockIdx.y, b = bh >> 3, nh = bh & 7;
    int i0 = blockIdx.x << 6, tid = threadIdx.x;
    const float* base = qkv + ((size_t)b * 3 * CC + nh * 192) * PP;
    for (int which = 0; which < 3; which++) {
        const float* src = base + (size_t)which * 64 * PP;
        float scale = (which == 0) ? 0.125f : 1.0f;
        __nv_bfloat16* dh = (which == 0 ? g_qhi : which == 1 ? g_khi : g_vhi) + (size_t)bh * PP * 64;
        __nv_bfloat16* dl = (which == 0 ? g_qlo : which == 1 ? g_klo : g_vlo) + (size_t)bh * PP * 64;
        __syncthreads();
        for (int idx = tid; idx < 1024; idx += 256) {
            int r = idx >> 4, c = idx & 15;
            float4 v = *(const float4*)(src + (size_t)r * PP + i0 + c * 4);
            ts[r][c * 4] = v.x * scale; ts[r][c * 4 + 1] = v.y * scale;
            ts[r][c * 4 + 2] = v.z * scale; ts[r][c * 4 + 3] = v.w * scale;
        }
        __syncthreads();
        for (int idx = tid; idx < 512; idx += 256) {
            int i = idx >> 3, c8 = idx & 7;
            unsigned short hi[8], lo[8];
#pragma unroll
            for (int k = 0; k < 8; k++) {
                float v = ts[c8 * 8 + k][i];
                __nv_bfloat16 h = __float2bfloat16_rn(v);
                hi[k] = bfu(h);
                lo[k] = bfu(__float2bfloat16_rn(v - __bfloat162float(h)));
            }
            *(uint4*)(dh + (size_t)(i0 + i) * 64 + c8 * 8) = *(uint4*)hi;
            *(uint4*)(dl + (size_t)(i0 + i) * 64 + c8 * 8) = *(uint4*)lo;
        }
    }
}

// --------------------- wmma bf16 flash attention ---------------------------
// smem map (bytes): Qh 0, Ql 18432, KV double-buf 36864 (2x36864),
// Ph 110592, Pl 129024, S float 147456 (34816), L 182272 -> total 182784
#define LDT 72               // bf16 tile leading dim (144B rows, 16B aligned)
#define LDSX 68              // float scratch leading dim
#define OFF_QH 0
#define OFF_QL 18432
#define OFF_KV 36864
#define KVBUF 36864
#define OFF_KH 0
#define OFF_KL 9216
#define OFF_VH 18432
#define OFF_VL 27648
#define OFF_PH 110592
#define OFF_PL 129024
#define OFF_S  147456
#define OFF_L  182272
#define ATTN_SMEM 182784

__device__ __forceinline__ void load_kv4(uint32_t kvb,
        const __nv_bfloat16* kh, const __nv_bfloat16* kl,
        const __nv_bfloat16* vh, const __nv_bfloat16* vl, int j0, int tid) {
    for (int idx = tid; idx < 512; idx += 256) {
        int r = idx >> 3, c = idx & 7;
        uint32_t d = (uint32_t)r * 144 + (uint32_t)c * 16;
        size_t srow = (size_t)(j0 + r) * 64 + c * 8;
        cpa16(kvb + OFF_KH + d, kh + srow);
        cpa16(kvb + OFF_KL + d, kl + srow);
        cpa16(kvb + OFF_VH + d, vh + srow);
        cpa16(kvb + OFF_VL + d, vl + srow);
    }
}

__global__ __launch_bounds__(256, 1) void attn_wmma(
        const __nv_bfloat16* __restrict__ qhi, const __nv_bfloat16* __restrict__ qlo,
        const __nv_bfloat16* __restrict__ khi, const __nv_bfloat16* __restrict__ klo,
        const __nv_bfloat16* __restrict__ vhi, const __nv_bfloat16* __restrict__ vlo,
        float* __restrict__ att) {
    extern __shared__ char sm[];
    uint32_t sb = smem_u32(sm);
    int tid = threadIdx.x, w = tid >> 5, lane = tid & 31;
    int bh = blockIdx.y, b = bh >> 3, nh = bh & 7;
    int i0 = blockIdx.x << 7;

    const __nv_bfloat16* qh = qhi + ((size_t)bh * PP + i0) * 64;
    const __nv_bfloat16* ql = qlo + ((size_t)bh * PP + i0) * 64;
    const __nv_bfloat16* kh = khi + (size_t)bh * PP * 64;
    const __nv_bfloat16* kl = klo + (size_t)bh * PP * 64;
    const __nv_bfloat16* vh = vhi + (size_t)bh * PP * 64;
    const __nv_bfloat16* vl = vlo + (size_t)bh * PP * 64;

    // Q tiles (128 rows) + first KV tile
    for (int idx = tid; idx < 1024; idx += 256) {
        int r = idx >> 3, c = idx & 7;
        uint32_t d = (uint32_t)r * 144 + (uint32_t)c * 16;
        cpa16(sb + OFF_QH + d, qh + (size_t)r * 64 + c * 8);
        cpa16(sb + OFF_QL + d, ql + (size_t)r * 64 + c * 8);
    }
    load_kv4(sb + OFF_KV, kh, kl, vh, vl, 0, tid);
    CPA_COMMIT();

    wmma::fragment<wmma::accumulator, 16, 16, 16, float> Oacc[4];
#pragma unroll
    for (int i = 0; i < 4; i++) wmma::fill_fragment(Oacc[i], 0.f);
    float lsum = 0.f;

    const __nv_bfloat16* Qhp = (const __nv_bfloat16*)(sm + OFF_QH) + w * 16 * LDT;
    const __nv_bfloat16* Qlp = (const __nv_bfloat16*)(sm + OFF_QL) + w * 16 * LDT;
    __nv_bfloat16* Php = (__nv_bfloat16*)(sm + OFF_PH);
    __nv_bfloat16* Plp = (__nv_bfloat16*)(sm + OFF_PL);
    float* Ss = (float*)(sm + OFF_S);
    float* Ls = (float*)(sm + OFF_L);

    for (int t = 0; t < 64; t++) {
        __syncthreads();  // all warps done reading buffer to be overwritten
        if (t + 1 < 64) {
            load_kv4(sb + OFF_KV + ((t + 1) & 1) * KVBUF, kh, kl, vh, vl, (t + 1) * 64, tid);
            CPA_COMMIT();
            CPA_WAIT1();
        } else {
            CPA_WAIT0();
        }
        __syncthreads();
        const char* buf = sm + OFF_KV + (t & 1) * KVBUF;
        const __nv_bfloat16* Kh = (const __nv_bfloat16*)(buf + OFF_KH);
        const __nv_bfloat16* Kl = (const __nv_bfloat16*)(buf + OFF_KL);
        const __nv_bfloat16* Vh = (const __nv_bfloat16*)(buf + OFF_VH);
        const __nv_bfloat16* Vl = (const __nv_bfloat16*)(buf + OFF_VL);

        // ---- S = QK^T (3-term hi/lo) ----
        wmma::fragment<wmma::accumulator, 16, 16, 16, float> Sacc[4];
#pragma unroll
        for (int jn = 0; jn < 4; jn++) wmma::fill_fragment(Sacc[jn], 0.f);
#pragma unroll
        for (int kk = 0; kk < 4; kk++) {
            wmma::fragment<wmma::matrix_a, 16, 16, 16, __nv_bfloat16, wmma::row_major> Ah, Al;
            wmma::load_matrix_sync(Ah, Qhp + kk * 16, LDT);
            wmma::load_matrix_sync(Al, Qlp + kk * 16, LDT);
#pragma unroll
            for (int jn = 0; jn < 4; jn++) {
                wmma::fragment<wmma::matrix_b, 16, 16, 16, __nv_bfloat16, wmma::col_major> Bh, Bl;
                wmma::load_matrix_sync(Bh, Kh + jn * 16 * LDT + kk * 16, LDT);
                wmma::load_matrix_sync(Bl, Kl + jn * 16 * LDT + kk * 16, LDT);
                wmma::mma_sync(Sacc[jn], Ah, Bh, Sacc[jn]);
                wmma::mma_sync(Sacc[jn], Ah, Bl, Sacc[jn]);
                wmma::mma_sync(Sacc[jn], Al, Bh, Sacc[jn]);
            }
        }
#pragma unroll
        for (int jn = 0; jn < 4; jn++)
            wmma::store_matrix_sync(Ss + (w * 16) * LDSX + jn * 16, Sacc[jn], LDSX, wmma::mem_row_major);
        __syncwarp();

        // ---- exp + hi/lo split into P ----
        {
            int rloc = w * 16 + (lane >> 1), hcol = (lane & 1) * 32;
            const float* srow = Ss + rloc * LDSX + hcol;
            __nv_bfloat16* ph = Php + rloc * LDT + hcol;
            __nv_bfloat16* pl = Plp + rloc * LDT + hcol;
            float part = 0.f;
#pragma unroll
            for (int c = 0; c < 32; c++) {
                float e = __expf(srow[c]);
                part += e;
                __nv_bfloat16 ehi = __float2bfloat16_rn(e);
                ph[c] = ehi;
                pl[c] = __float2bfloat16_rn(e - __bfloat162float(ehi));
            }
            lsum += part;
        }
        __syncwarp();

        // ---- O += P V (3-term hi/lo) ----
#pragma unroll
        for (int kk = 0; kk < 4; kk++) {
            wmma::fragment<wmma::matrix_a, 16, 16, 16, __nv_bfloat16, wmma::row_major> Pa, Pb;
            wmma::load_matrix_sync(Pa, Php + (w * 16) * LDT + kk * 16, LDT);
            wmma::load_matrix_sync(Pb, Plp + (w * 16) * LDT + kk * 16, LDT);
#pragma unroll
            for (int dn = 0; dn < 4; dn++) {
                wmma::fragment<wmma::matrix_b, 16, 16, 16, __nv_bfloat16, wmma::row_major> Bh, Bl;
                wmma::load_matrix_sync(Bh, Vh + kk * 16 * LDT + dn * 16, LDT);
                wmma::load_matrix_sync(Bl, Vl + kk * 16 * LDT + dn * 16, LDT);
                wmma::mma_sync(Oacc[dn], Pa, Bh, Oacc[dn]);
                wmma::mma_sync(Oacc[dn], Pa, Bl, Oacc[dn]);
                wmma::mma_sync(Oacc[dn], Pb, Bh, Oacc[dn]);
            }
        }
    }

    // ---- finalize: store O, normalize, transpose to att[c][p] ----
    float l2 = lsum + __shfl_xor_sync(0xffffffffu, lsum, 1);
    if ((lane & 1) == 0) Ls[w * 16 + (lane >> 1)] = 1.f / l2;
#pragma unroll
    for (int dn = 0; dn < 4; dn++)
        wmma::store_matrix_sync(Ss + (w * 16) * LDSX + dn * 16, Oacc[dn], LDSX, wmma::mem_row_major);
    __syncthreads();
    float* ab = att + ((size_t)b * CC + nh * 64) * PP + i0;
    for (int idx = tid; idx < 2048; idx += 256) {
        int d = idx >> 5, i4 = (idx & 31) * 4;
        float4 o;
        o.x = Ss[(i4 + 0) * LDSX + d] * Ls[i4 + 0];
        o.y = Ss[(i4 + 1) * LDSX + d] * Ls[i4 + 1];
        o.z = Ss[(i4 + 2) * LDSX + d] * Ls[i4 + 2];
        o.w = Ss[(i4 + 3) * LDSX + d] * Ls[i4 + 3];
        *(float4*)(ab + (size_t)d * PP + i4) = o;
    }
}

// ---------------------------------------------------------------------------
extern "C" void kernel_launch(void* const* d_in, const int* in_sizes, int n_in,
                              void* d_out, int out_size) {
    const float* x = (const float*)d_in[0];
    const float* qkv_w = (const float*)d_in[1];
    const float* proj_w = (const float*)d_in[2];
    const float* proj_b = (const float*)d_in[3];
    const float* gn_w = (const float*)d_in[4];
    const float* gn_b = (const float*)d_in[5];
    float* out = (float*)d_out;

    float *hp, *qkvp, *attp;
    cudaGetSymbolAddress((void**)&hp, g_h);
    cudaGetSymbolAddress((void**)&qkvp, g_qkv);
    cudaGetSymbolAddress((void**)&attp, g_att);
    __nv_bfloat16 *qh, *ql, *kh, *kl, *vh, *vl;
    cudaGetSymbolAddress((void**)&qh, g_qhi);
    cudaGetSymbolAddress((void**)&ql, g_qlo);
    cudaGetSymbolAddress((void**)&kh, g_khi);
    cudaGetSymbolAddress((void**)&kl, g_klo);
    cudaGetSymbolAddress((void**)&vh, g_vhi);
    cudaGetSymbolAddress((void**)&vl, g_vlo);

    cudaFuncSetAttribute(attn_wmma, cudaFuncAttributeMaxDynamicSharedMemorySize, ATTN_SMEM);

    gn_kernel<<<BB * GG, 256>>>(x, gn_w, gn_b, hp);
    gemm64<<<dim3(PP / 64, (3 * CC) / 64, BB), 256>>>(qkv_w, hp, qkvp, nullptr, nullptr, 3 * CC);
    prep_kernel<<<dim3(PP / 64, NBH), 256>>>(qkvp);
    attn_wmma<<<dim3(PP / 128, NBH), 256, ATTN_SMEM>>>(qh, ql, kh, kl, vh, vl, attp);
    gemm64<<<dim3(PP / 64, CC / 64, BB), 256>>>(proj_w, attp, out, proj_b, x, CC);
}

// round 5
// speedup vs baseline: 2.6753x; 1.3494x over previous
#include <cuda_runtime.h>
#include <cuda_bf16.h>
#include <mma.h>
#include <math.h>
#include <stdint.h>
using namespace nvcuda;

#define BB 2
#define CC 512
#define PP 4096
#define NBH 16
#define GG 32
#define CPG 16
#define EPSV 1e-5f

__device__ float g_att[BB * CC * PP];
__device__ __align__(16) __nv_bfloat16 g_hhi[BB * CC * PP];
__device__ __align__(16) __nv_bfloat16 g_hlo[BB * CC * PP];
__device__ __align__(16) __nv_bfloat16 g_wqh[3 * CC * CC];
__device__ __align__(16) __nv_bfloat16 g_wql[3 * CC * CC];
__device__ __align__(16) __nv_bfloat16 g_qhi[NBH * PP * 64];
__device__ __align__(16) __nv_bfloat16 g_qlo[NBH * PP * 64];
__device__ __align__(16) __nv_bfloat16 g_khi[NBH * PP * 64];
__device__ __align__(16) __nv_bfloat16 g_klo[NBH * PP * 64];
__device__ __align__(16) __nv_bfloat16 g_vhi[NBH * PP * 64];
__device__ __align__(16) __nv_bfloat16 g_vlo[NBH * PP * 64];

__device__ __forceinline__ uint32_t smem_u32(const void* p) {
    uint32_t a;
    asm("{ .reg .u64 t; cvta.to.shared.u64 t, %1; cvt.u32.u64 %0, t; }" : "=r"(a) : "l"(p));
    return a;
}
__device__ __forceinline__ void cpa16(uint32_t dst, const void* src) {
    asm volatile("cp.async.cg.shared.global [%0], [%1], 16;" :: "r"(dst), "l"(src));
}
#define CPA_COMMIT() asm volatile("cp.async.commit_group;" ::: "memory")
#define CPA_WAIT1()  asm volatile("cp.async.wait_group 1;" ::: "memory")
#define CPA_WAIT0()  asm volatile("cp.async.wait_group 0;" ::: "memory")
__device__ __forceinline__ unsigned short bfu(__nv_bfloat16 x) { return *(unsigned short*)&x; }
__device__ __forceinline__ uint32_t pack2(float a, float b) {
    __nv_bfloat16 ha = __float2bfloat16_rn(a), hb = __float2bfloat16_rn(b);
    return (uint32_t)bfu(ha) | ((uint32_t)bfu(hb) << 16);
}

// --------- GroupNorm -> bf16 hi/lo output ---------------------------------
__global__ __launch_bounds__(256) void gn_kernel(const float* __restrict__ x,
        const float* __restrict__ gw, const float* __restrict__ gb) {
    int b = blockIdx.x / GG, g = blockIdx.x % GG;
    size_t base = ((size_t)b * CC + g * CPG) * PP;
    const float4* xp = (const float4*)(x + base);
    const int N4 = CPG * PP / 4;
    float s = 0.f, s2 = 0.f;
    for (int i = threadIdx.x; i < N4; i += 256) {
        float4 v = xp[i];
        s += v.x + v.y + v.z + v.w;
        s2 += v.x * v.x + v.y * v.y + v.z * v.z + v.w * v.w;
    }
    __shared__ float rs[256], rs2[256];
    rs[threadIdx.x] = s; rs2[threadIdx.x] = s2;
    __syncthreads();
    for (int o = 128; o > 0; o >>= 1) {
        if (threadIdx.x < o) { rs[threadIdx.x] += rs[threadIdx.x + o]; rs2[threadIdx.x] += rs2[threadIdx.x + o]; }
        __syncthreads();
    }
    __shared__ float sm2[2];
    if (threadIdx.x == 0) {
        float mean = rs[0] / (float)(CPG * PP);
        sm2[0] = mean; sm2[1] = rsqrtf(rs2[0] / (float)(CPG * PP) - mean * mean + EPSV);
    }
    __syncthreads();
    float mean = sm2[0], rstd = sm2[1];
    for (int i = threadIdx.x; i < N4; i += 256) {
        int c = g * CPG + (i >> 10);
        float ga = gw[c] * rstd, be = gb[c];
        float4 v = xp[i];
        float vv[4] = {(v.x - mean) * ga + be, (v.y - mean) * ga + be,
                       (v.z - mean) * ga + be, (v.w - mean) * ga + be};
        unsigned short hh[4], ll[4];
#pragma unroll
        for (int k = 0; k < 4; k++) {
            __nv_bfloat16 h = __float2bfloat16_rn(vv[k]);
            hh[k] = bfu(h);
            ll[k] = bfu(__float2bfloat16_rn(vv[k] - __bfloat162float(h)));
        }
        *(uint2*)(g_hhi + base + i * 4) = *(uint2*)hh;
        *(uint2*)(g_hlo + base + i * 4) = *(uint2*)ll;
    }
}

// --------- split qkv_w into bf16 hi/lo ------------------------------------
__global__ __launch_bounds__(256) void wsplit_kernel(const float* __restrict__ w) {
    int n = 3 * CC * CC;
    for (int i = blockIdx.x * 256 + threadIdx.x; i < n; i += gridDim.x * 256) {
        float v = w[i];
        __nv_bfloat16 h = __float2bfloat16_rn(v);
        g_wqh[i] = h;
        g_wql[i] = __float2bfloat16_rn(v - __bfloat162float(h));
    }
}

// --------- QKV GEMM (wmma hi/lo) with fused split/transpose epilogue ------
// CTA: 64 o-rows (one q/k/v block of one head) x 128 p. 8 warps (16o x 64p).
#define QLDW 40
#define QLDH 136
#define QSTG 27648   // one stage: Wh 5120 + Wl 5120 + Hh 8704 + Hl 8704
#define QW_WL 5120
#define QW_HH 10240
#define QW_HL 18944
#define QLDE 132
#define QKV_SMEM (2 * QSTG)

__global__ __launch_bounds__(256) void qkv_wmma(const float* __restrict__ dummy) {
    extern __shared__ char sm[];
    uint32_t sb = smem_u32(sm);
    int tid = threadIdx.x, w = tid >> 5;
    int p0 = blockIdx.x << 7;
    int nh = blockIdx.y / 3, part = blockIdx.y % 3;
    int o0 = blockIdx.y << 6;
    int b = blockIdx.z, bh = b * 8 + nh;
    int osub = w >> 1, ph = w & 1;

    const __nv_bfloat16* Wh = g_wqh + (size_t)o0 * CC;
    const __nv_bfloat16* Wl = g_wql + (size_t)o0 * CC;
    const __nv_bfloat16* Hh = g_hhi + (size_t)b * CC * PP;
    const __nv_bfloat16* Hl = g_hlo + (size_t)b * CC * PP;

    // stage loader for k-chunk kc (32 channels)
    auto stage = [&](int buf, int k0) {
        uint32_t bs = sb + buf * QSTG;
        // W: 64 rows x 4 c8 x 2
        for (int idx = tid; idx < 512; idx += 256) {
            int m = idx >> 8, r = (idx >> 2) & 63, c8 = idx & 3;
            uint32_t d = bs + m * QW_WL + r * 80 + c8 * 16;
            const __nv_bfloat16* src = (m ? Wl : Wh) + (size_t)r * CC + k0 + c8 * 8;
            cpa16(d, src);
        }
        // H: 32 rows x 16 c8 x 2
        for (int idx = tid; idx < 1024; idx += 256) {
            int m = idx >> 9, r = (idx >> 4) & 31, c8 = idx & 15;
            uint32_t d = bs + QW_HH + m * 8704 + r * 272 + c8 * 16;
            const __nv_bfloat16* src = (m ? Hl : Hh) + (size_t)(k0 + r) * PP + p0 + c8 * 8;
            cpa16(d, src);
        }
    };

    wmma::fragment<wmma::accumulator, 16, 16, 16, float> Cacc[4];
#pragma unroll
    for (int i = 0; i < 4; i++) wmma::fill_fragment(Cacc[i], 0.f);

    stage(0, 0);
    CPA_COMMIT();
    for (int kc = 0; kc < 16; kc++) {
        __syncthreads();
        if (kc + 1 < 16) { stage((kc + 1) & 1, (kc + 1) * 32); CPA_COMMIT(); CPA_WAIT1(); }
        else CPA_WAIT0();
        __syncthreads();
        const char* bs = sm + (kc & 1) * QSTG;
        const __nv_bfloat16* wh = (const __nv_bfloat16*)bs;
        const __nv_bfloat16* wl = (const __nv_bfloat16*)(bs + QW_WL);
        const __nv_bfloat16* hh = (const __nv_bfloat16*)(bs + QW_HH);
        const __nv_bfloat16* hl = (const __nv_bfloat16*)(bs + QW_HL);
#pragma unroll
        for (int kk = 0; kk < 2; kk++) {
            wmma::fragment<wmma::matrix_a, 16, 16, 16, __nv_bfloat16, wmma::row_major> Ah, Al;
            wmma::load_matrix_sync(Ah, wh + (osub * 16) * QLDW + kk * 16, QLDW);
            wmma::load_matrix_sync(Al, wl + (osub * 16) * QLDW + kk * 16, QLDW);
#pragma unroll
            for (int jn = 0; jn < 4; jn++) {
                wmma::fragment<wmma::matrix_b, 16, 16, 16, __nv_bfloat16, wmma::row_major> Bh, Bl;
                const __nv_bfloat16* hb = hh + (kk * 16) * QLDH + ph * 64 + jn * 16;
                const __nv_bfloat16* lb = hl + (kk * 16) * QLDH + ph * 64 + jn * 16;
                wmma::load_matrix_sync(Bh, hb, QLDH);
                wmma::load_matrix_sync(Bl, lb, QLDH);
                wmma::mma_sync(Cacc[jn], Ah, Bh, Cacc[jn]);
                wmma::mma_sync(Cacc[jn], Ah, Bl, Cacc[jn]);
                wmma::mma_sync(Cacc[jn], Al, Bh, Cacc[jn]);
            }
        }
    }
    // epilogue: smem [o][p] f32, then transpose-split to token-major hi/lo
    __syncthreads();
    float* Es = (float*)sm;
#pragma unroll
    for (int jn = 0; jn < 4; jn++)
        wmma::store_matrix_sync(Es + (osub * 16) * QLDE + ph * 64 + jn * 16, Cacc[jn], QLDE, wmma::mem_row_major);
    __syncthreads();
    __nv_bfloat16* dh = (part == 0 ? g_qhi : part == 1 ? g_khi : g_vhi) + (size_t)bh * PP * 64;
    __nv_bfloat16* dl = (part == 0 ? g_qlo : part == 1 ? g_klo : g_vlo) + (size_t)bh * PP * 64;
    float scale = (part == 0) ? 0.125f : 1.0f;
    for (int idx = tid; idx < 2048; idx += 256) {
        int p = idx >> 4, d4 = (idx & 15) << 2;
        unsigned short hh[4], ll[4];
#pragma unroll
        for (int j = 0; j < 4; j++) {
            float v = Es[(d4 + j) * QLDE + p] * scale;
            __nv_bfloat16 h = __float2bfloat16_rn(v);
            hh[j] = bfu(h);
            ll[j] = bfu(__float2bfloat16_rn(v - __bfloat162float(h)));
        }
        size_t off = (size_t)(p0 + p) * 64 + d4;
        *(uint2*)(dh + off) = *(uint2*)hh;
        *(uint2*)(dl + off) = *(uint2*)ll;
    }
}

// ------------------------- SIMT proj GEMM (unchanged) ----------------------
__global__ __launch_bounds__(256) void gemm64(const float* __restrict__ W, const float* __restrict__ In,
        float* __restrict__ Out, const float* __restrict__ bias, const float* __restrict__ resid, int Mrows) {
    __shared__ float Ws[16][64];
    __shared__ float Hs[16][64];
    int tid = threadIdx.x, b = blockIdx.z;
    int o0 = blockIdx.y << 6, p0 = blockIdx.x << 6;
    const float* Wp = W + (size_t)o0 * CC;
    const float* Ip = In + (size_t)b * CC * PP + p0;
    int ty = tid >> 4, tx = tid & 15;
    int wrow = tid >> 2, wq = (tid & 3) << 2;
    int hk = tid >> 4, hq = (tid & 15) << 2;
    float acc[4][4] = {};
    for (int k0 = 0; k0 < CC; k0 += 16) {
        __syncthreads();
        float4 w4 = *(const float4*)(Wp + (size_t)wrow * CC + k0 + wq);
        Ws[wq][wrow] = w4.x; Ws[wq + 1][wrow] = w4.y; Ws[wq + 2][wrow] = w4.z; Ws[wq + 3][wrow] = w4.w;
        *(float4*)&Hs[hk][hq] = *(const float4*)(Ip + (size_t)(k0 + hk) * PP + hq);
        __syncthreads();
#pragma unroll
        for (int kk = 0; kk < 16; kk++) {
            float4 a = *(float4*)&Ws[kk][ty << 2];
            float4 h = *(float4*)&Hs[kk][tx << 2];
            const float *af = (const float*)&a, *hf = (const float*)&h;
#pragma unroll
            for (int r = 0; r < 4; r++)
#pragma unroll
                for (int u = 0; u < 4; u++) acc[r][u] += af[r] * hf[u];
        }
    }
#pragma unroll
    for (int r = 0; r < 4; r++) {
        int o = o0 + (ty << 2) + r;
        float bv = bias ? bias[o] : 0.f;
        size_t off = ((size_t)b * Mrows + o) * PP + p0 + (tx << 2);
        float4 v = make_float4(acc[r][0] + bv, acc[r][1] + bv, acc[r][2] + bv, acc[r][3] + bv);
        if (resid) { float4 rr = *(const float4*)(resid + off); v.x += rr.x; v.y += rr.y; v.z += rr.z; v.w += rr.w; }
        *(float4*)(Out + off) = v;
    }
}

// --------- attention: 512 threads, 256 q-rows, reg-resident Q, P overlay ---
#define LDT 72
#define LDSX 68
#define KVBUF 36864        // Kh 9216 | Kl 9216 | Vh 9216 | Vl 9216
#define OFF_S 73728        // 256 rows x 68 f32 = 69632
#define OFF_L 143360
#define ATTN_SMEM 144384

__device__ __forceinline__ void load_kv4(uint32_t base,
        const __nv_bfloat16* kh, const __nv_bfloat16* kl,
        const __nv_bfloat16* vh, const __nv_bfloat16* vl, int j0, int tid) {
    for (int idx = tid; idx < 2048; idx += 512) {
        int m = idx >> 9, r = (idx >> 3) & 63, c8 = idx & 7;
        uint32_t d = base + m * 9216 + r * 144 + c8 * 16;
        const __nv_bfloat16* s = (m == 0 ? kh : m == 1 ? kl : m == 2 ? vh : vl) + (size_t)(j0 + r) * 64 + c8 * 8;
        cpa16(d, s);
    }
}

__global__ __launch_bounds__(512) void attn_wmma2(float* __restrict__ att) {
    extern __shared__ char sm[];
    uint32_t sb = smem_u32(sm);
    int tid = threadIdx.x, w = tid >> 5, lane = tid & 31;
    int bh = blockIdx.y, b = bh >> 3, nh = bh & 7;
    int i0 = blockIdx.x << 8;  // 256-row q tile

    const __nv_bfloat16* qh = g_qhi + ((size_t)bh * PP + i0) * 64;
    const __nv_bfloat16* ql = g_qlo + ((size_t)bh * PP + i0) * 64;
    const __nv_bfloat16* kh = g_khi + (size_t)bh * PP * 64;
    const __nv_bfloat16* kl = g_klo + (size_t)bh * PP * 64;
    const __nv_bfloat16* vh = g_vhi + (size_t)bh * PP * 64;
    const __nv_bfloat16* vl = g_vlo + (size_t)bh * PP * 64;

    // stage Q into KV area, extract register fragments
    for (int idx = tid; idx < 4096; idx += 512) {
        int m = idx >> 11, r = (idx >> 3) & 255, c8 = idx & 7;
        uint32_t d = sb + m * 36864 + r * 144 + c8 * 16;
        const __nv_bfloat16* s = (m ? ql : qh) + (size_t)r * 64 + c8 * 8;
        cpa16(d, s);
    }
    CPA_COMMIT();
    CPA_WAIT0();
    __syncthreads();
    wmma::fragment<wmma::matrix_a, 16, 16, 16, __nv_bfloat16, wmma::row_major> Qh[4], Ql[4];
#pragma unroll
    for (int kk = 0; kk < 4; kk++) {
        wmma::load_matrix_sync(Qh[kk], (const __nv_bfloat16*)sm + (w * 16) * LDT + kk * 16, LDT);
        wmma::load_matrix_sync(Ql[kk], (const __nv_bfloat16*)(sm + 36864) + (w * 16) * LDT + kk * 16, LDT);
    }
    __syncthreads();
    load_kv4(sb, kh, kl, vh, vl, 0, tid);
    CPA_COMMIT();

    wmma::fragment<wmma::accumulator, 16, 16, 16, float> Oacc[4];
#pragma unroll
    for (int i = 0; i < 4; i++) wmma::fill_fragment(Oacc[i], 0.f);
    float lsum = 0.f;
    float* Ss = (float*)(sm + OFF_S);
    __nv_bfloat16* Pb16 = (__nv_bfloat16*)(sm + OFF_S);
    float* Ls = (float*)(sm + OFF_L);
    int rloc = w * 16 + (lane >> 1), hcol = (lane & 1) * 32;

    for (int t = 0; t < 64; t++) {
        __syncthreads();
        if (t + 1 < 64) {
            load_kv4(sb + ((t + 1) & 1) * KVBUF, kh, kl, vh, vl, (t + 1) * 64, tid);
            CPA_COMMIT(); CPA_WAIT1();
        } else CPA_WAIT0();
        __syncthreads();
        const char* buf = sm + (t & 1) * KVBUF;
        const __nv_bfloat16* Kh = (const __nv_bfloat16*)buf;
        const __nv_bfloat16* Kl = (const __nv_bfloat16*)(buf + 9216);
        const __nv_bfloat16* Vh = (const __nv_bfloat16*)(buf + 18432);
        const __nv_bfloat16* Vl = (const __nv_bfloat16*)(buf + 27648);

        // S = QK^T
        wmma::fragment<wmma::accumulator, 16, 16, 16, float> Sacc[4];
#pragma unroll
        for (int jn = 0; jn < 4; jn++) wmma::fill_fragment(Sacc[jn], 0.f);
#pragma unroll
        for (int kk = 0; kk < 4; kk++) {
#pragma unroll
            for (int jn = 0; jn < 4; jn++) {
                wmma::fragment<wmma::matrix_b, 16, 16, 16, __nv_bfloat16, wmma::col_major> Bh, Bl;
                wmma::load_matrix_sync(Bh, Kh + jn * 16 * LDT + kk * 16, LDT);
                wmma::load_matrix_sync(Bl, Kl + jn * 16 * LDT + kk * 16, LDT);
                wmma::mma_sync(Sacc[jn], Qh[kk], Bh, Sacc[jn]);
                wmma::mma_sync(Sacc[jn], Qh[kk], Bl, Sacc[jn]);
                wmma::mma_sync(Sacc[jn], Ql[kk], Bh, Sacc[jn]);
            }
        }
#pragma unroll
        for (int jn = 0; jn < 4; jn++)
            wmma::store_matrix_sync(Ss + (w * 16) * LDSX + jn * 16, Sacc[jn], LDSX, wmma::mem_row_major);
        __syncwarp();
        // exp + hi/lo split; P overlays S rows (warp-private)
        {
            const float* srow = Ss + rloc * LDSX + hcol;
            float ev[32];
#pragma unroll
            for (int c8 = 0; c8 < 8; c8++) *(float4*)(ev + c8 * 4) = *(const float4*)(srow + c8 * 4);
            __syncwarp();
            uint32_t* ph = (uint32_t*)(Pb16 + rloc * 136 + hcol);
            uint32_t* pl = (uint32_t*)(Pb16 + rloc * 136 + 64 + hcol);
            float part = 0.f;
#pragma unroll
            for (int c2 = 0; c2 < 16; c2++) {
                float e0 = __expf(ev[2 * c2]), e1 = __expf(ev[2 * c2 + 1]);
                part += e0 + e1;
                __nv_bfloat16 h0 = __float2bfloat16_rn(e0), h1 = __float2bfloat16_rn(e1);
                ph[c2] = (uint32_t)bfu(h0) | ((uint32_t)bfu(h1) << 16);
                pl[c2] = pack2(e0 - __bfloat162float(h0), e1 - __bfloat162float(h1));
            }
            lsum += part;
        }
        __syncwarp();
        // O += P V
#pragma unroll
        for (int kk = 0; kk < 4; kk++) {
            wmma::fragment<wmma::matrix_a, 16, 16, 16, __nv_bfloat16, wmma::row_major> Pa, Pb;
            wmma::load_matrix_sync(Pa, Pb16 + (w * 16) * 136 + kk * 16, 136);
            wmma::load_matrix_sync(Pb, Pb16 + (w * 16) * 136 + 64 + kk * 16, 136);
#pragma unroll
            for (int dn = 0; dn < 4; dn++) {
                wmma::fragment<wmma::matrix_b, 16, 16, 16, __nv_bfloat16, wmma::row_major> Bh, Bl;
                wmma::load_matrix_sync(Bh, Vh + kk * 16 * LDT + dn * 16, LDT);
                wmma::load_matrix_sync(Bl, Vl + kk * 16 * LDT + dn * 16, LDT);
                wmma::mma_sync(Oacc[dn], Pa, Bh, Oacc[dn]);
                wmma::mma_sync(Oacc[dn], Pa, Bl, Oacc[dn]);
                wmma::mma_sync(Oacc[dn], Pb, Bh, Oacc[dn]);
            }
        }
    }

    // finalize
    float l2 = lsum + __shfl_xor_sync(0xffffffffu, lsum, 1);
    if ((lane & 1) == 0) Ls[rloc] = 1.f / l2;
    __syncthreads();
#pragma unroll
    for (int dn = 0; dn < 4; dn++)
        wmma::store_matrix_sync(Ss + (w * 16) * LDSX + dn * 16, Oacc[dn], LDSX, wmma::mem_row_major);
    __syncthreads();
    float* ab = att + ((size_t)b * CC + nh * 64) * PP + i0;
    for (int idx = tid; idx < 4096; idx += 512) {
        int d = idx >> 6, i4 = (idx & 63) << 2;
        float4 o;
        o.x = Ss[(i4 + 0) * LDSX + d] * Ls[i4 + 0];
        o.y = Ss[(i4 + 1) * LDSX + d] * Ls[i4 + 1];
        o.z = Ss[(i4 + 2) * LDSX + d] * Ls[i4 + 2];
        o.w = Ss[(i4 + 3) * LDSX + d] * Ls[i4 + 3];
        *(float4*)(ab + (size_t)d * PP + i4) = o;
    }
}

// ---------------------------------------------------------------------------
extern "C" void kernel_launch(void* const* d_in, const int* in_sizes, int n_in,
                              void* d_out, int out_size) {
    const float* x = (const float*)d_in[0];
    const float* qkv_w = (const float*)d_in[1];
    const float* proj_w = (const float*)d_in[2];
    const float* proj_b = (const float*)d_in[3];
    const float* gn_w = (const float*)d_in[4];
    const float* gn_b = (const float*)d_in[5];
    float* out = (float*)d_out;

    float* attp;
    cudaGetSymbolAddress((void**)&attp, g_att);

    cudaFuncSetAttribute(qkv_wmma, cudaFuncAttributeMaxDynamicSharedMemorySize, QKV_SMEM);
    cudaFuncSetAttribute(attn_wmma2, cudaFuncAttributeMaxDynamicSharedMemorySize, ATTN_SMEM);

    gn_kernel<<<BB * GG, 256>>>(x, gn_w, gn_b);
    wsplit_kernel<<<768, 256>>>(qkv_w);
    qkv_wmma<<<dim3(PP / 128, 24, BB), 256, QKV_SMEM>>>(nullptr);
    attn_wmma2<<<dim3(PP / 256, NBH), 512, ATTN_SMEM>>>(attp);
    gemm64<<<dim3(PP / 64, CC / 64, BB), 256>>>(proj_w, attp, out, proj_b, x, CC);
}

// round 6
// speedup vs baseline: 3.8268x; 1.4304x over previous
#include <cuda_runtime.h>
#include <cuda_bf16.h>
#include <mma.h>
#include <math.h>
#include <stdint.h>
using namespace nvcuda;

#define BB 2
#define CC 512
#define PP 4096
#define NBH 16
#define GG 32
#define CPG 16
#define EPSV 1e-5f

__device__ float g_att[BB * CC * PP];
__device__ __align__(16) __nv_bfloat16 g_hhi[BB * CC * PP];
__device__ __align__(16) __nv_bfloat16 g_hlo[BB * CC * PP];
__device__ __align__(16) __nv_bfloat16 g_wqh[3 * CC * CC];
__device__ __align__(16) __nv_bfloat16 g_wql[3 * CC * CC];
__device__ __align__(16) __nv_bfloat16 g_qhi[NBH * PP * 64];
__device__ __align__(16) __nv_bfloat16 g_qlo[NBH * PP * 64];
__device__ __align__(16) __nv_bfloat16 g_khi[NBH * PP * 64];
__device__ __align__(16) __nv_bfloat16 g_klo[NBH * PP * 64];
__device__ __align__(16) __nv_bfloat16 g_vhi[NBH * PP * 64];
__device__ __align__(16) __nv_bfloat16 g_vlo[NBH * PP * 64];

__device__ __forceinline__ uint32_t smem_u32(const void* p) {
    uint32_t a;
    asm("{ .reg .u64 t; cvta.to.shared.u64 t, %1; cvt.u32.u64 %0, t; }" : "=r"(a) : "l"(p));
    return a;
}
__device__ __forceinline__ void cpa16(uint32_t dst, const void* src) {
    asm volatile("cp.async.cg.shared.global [%0], [%1], 16;" :: "r"(dst), "l"(src));
}
#define CPA_COMMIT() asm volatile("cp.async.commit_group;" ::: "memory")
#define CPA_WAIT1()  asm volatile("cp.async.wait_group 1;" ::: "memory")
#define CPA_WAIT0()  asm volatile("cp.async.wait_group 0;" ::: "memory")
__device__ __forceinline__ unsigned short bfu(__nv_bfloat16 x) { return *(unsigned short*)&x; }
__device__ __forceinline__ uint32_t pack2(float a, float b) {
    __nv_bfloat16 ha = __float2bfloat16_rn(a), hb = __float2bfloat16_rn(b);
    return (uint32_t)bfu(ha) | ((uint32_t)bfu(hb) << 16);
}
__device__ __forceinline__ void ldsm4(uint32_t* r, uint32_t a) {
    asm volatile("ldmatrix.sync.aligned.m8n8.x4.shared.b16 {%0,%1,%2,%3}, [%4];"
        : "=r"(r[0]), "=r"(r[1]), "=r"(r[2]), "=r"(r[3]) : "r"(a));
}
__device__ __forceinline__ void ldsm4t(uint32_t* r, uint32_t a) {
    asm volatile("ldmatrix.sync.aligned.m8n8.x4.trans.shared.b16 {%0,%1,%2,%3}, [%4];"
        : "=r"(r[0]), "=r"(r[1]), "=r"(r[2]), "=r"(r[3]) : "r"(a));
}
__device__ __forceinline__ void mma16816(float* c, const uint32_t* a, uint32_t b0, uint32_t b1) {
    asm volatile("mma.sync.aligned.m16n8k16.row.col.f32.bf16.bf16.f32 "
        "{%0,%1,%2,%3}, {%4,%5,%6,%7}, {%8,%9}, {%0,%1,%2,%3};"
        : "+f"(c[0]), "+f"(c[1]), "+f"(c[2]), "+f"(c[3])
        : "r"(a[0]), "r"(a[1]), "r"(a[2]), "r"(a[3]), "r"(b0), "r"(b1));
}

// --------- GroupNorm -> bf16 hi/lo ----------------------------------------
__global__ __launch_bounds__(256) void gn_kernel(const float* __restrict__ x,
        const float* __restrict__ gw, const float* __restrict__ gb) {
    int b = blockIdx.x / GG, g = blockIdx.x % GG;
    size_t base = ((size_t)b * CC + g * CPG) * PP;
    const float4* xp = (const float4*)(x + base);
    const int N4 = CPG * PP / 4;
    float s = 0.f, s2 = 0.f;
    for (int i = threadIdx.x; i < N4; i += 256) {
        float4 v = xp[i];
        s += v.x + v.y + v.z + v.w;
        s2 += v.x * v.x + v.y * v.y + v.z * v.z + v.w * v.w;
    }
    __shared__ float rs[256], rs2[256];
    rs[threadIdx.x] = s; rs2[threadIdx.x] = s2;
    __syncthreads();
    for (int o = 128; o > 0; o >>= 1) {
        if (threadIdx.x < o) { rs[threadIdx.x] += rs[threadIdx.x + o]; rs2[threadIdx.x] += rs2[threadIdx.x + o]; }
        __syncthreads();
    }
    __shared__ float sm2[2];
    if (threadIdx.x == 0) {
        float mean = rs[0] / (float)(CPG * PP);
        sm2[0] = mean; sm2[1] = rsqrtf(rs2[0] / (float)(CPG * PP) - mean * mean + EPSV);
    }
    __syncthreads();
    float mean = sm2[0], rstd = sm2[1];
    for (int i = threadIdx.x; i < N4; i += 256) {
        int c = g * CPG + (i >> 10);
        float ga = gw[c] * rstd, be = gb[c];
        float4 v = xp[i];
        float vv[4] = {(v.x - mean) * ga + be, (v.y - mean) * ga + be,
                       (v.z - mean) * ga + be, (v.w - mean) * ga + be};
        unsigned short hh[4], ll[4];
#pragma unroll
        for (int k = 0; k < 4; k++) {
            __nv_bfloat16 h = __float2bfloat16_rn(vv[k]);
            hh[k] = bfu(h);
            ll[k] = bfu(__float2bfloat16_rn(vv[k] - __bfloat162float(h)));
        }
        *(uint2*)(g_hhi + base + i * 4) = *(uint2*)hh;
        *(uint2*)(g_hlo + base + i * 4) = *(uint2*)ll;
    }
}

// --------- split qkv_w into bf16 hi/lo ------------------------------------
__global__ __launch_bounds__(256) void wsplit_kernel(const float* __restrict__ w) {
    int n = 3 * CC * CC;
    for (int i = blockIdx.x * 256 + threadIdx.x; i < n; i += gridDim.x * 256) {
        float v = w[i];
        __nv_bfloat16 h = __float2bfloat16_rn(v);
        g_wqh[i] = h;
        g_wql[i] = __float2bfloat16_rn(v - __bfloat162float(h));
    }
}

// --------- QKV GEMM (wmma hi/lo) + fused split/transpose epilogue ---------
#define QLDW 40
#define QLDH 136
#define QSTG 27648
#define QW_WL 5120
#define QW_HH 10240
#define QW_HL 18944
#define QLDE 132
#define QKV_SMEM (2 * QSTG)

__global__ __launch_bounds__(256) void qkv_wmma(const float* __restrict__ dummy) {
    extern __shared__ char sm[];
    uint32_t sb = smem_u32(sm);
    int tid = threadIdx.x, w = tid >> 5;
    int p0 = blockIdx.x << 7;
    int nh = blockIdx.y / 3, part = blockIdx.y % 3;
    int o0 = blockIdx.y << 6;
    int b = blockIdx.z, bh = b * 8 + nh;
    int osub = w >> 1, ph = w & 1;

    const __nv_bfloat16* Wh = g_wqh + (size_t)o0 * CC;
    const __nv_bfloat16* Wl = g_wql + (size_t)o0 * CC;
    const __nv_bfloat16* Hh = g_hhi + (size_t)b * CC * PP;
    const __nv_bfloat16* Hl = g_hlo + (size_t)b * CC * PP;

    auto stage = [&](int buf, int k0) {
        uint32_t bs = sb + buf * QSTG;
        for (int idx = tid; idx < 512; idx += 256) {
            int m = idx >> 8, r = (idx >> 2) & 63, c8 = idx & 3;
            uint32_t d = bs + m * QW_WL + r * 80 + c8 * 16;
            const __nv_bfloat16* src = (m ? Wl : Wh) + (size_t)r * CC + k0 + c8 * 8;
            cpa16(d, src);
        }
        for (int idx = tid; idx < 1024; idx += 256) {
            int m = idx >> 9, r = (idx >> 4) & 31, c8 = idx & 15;
            uint32_t d = bs + QW_HH + m * 8704 + r * 272 + c8 * 16;
            const __nv_bfloat16* src = (m ? Hl : Hh) + (size_t)(k0 + r) * PP + p0 + c8 * 8;
            cpa16(d, src);
        }
    };

    wmma::fragment<wmma::accumulator, 16, 16, 16, float> Cacc[4];
#pragma unroll
    for (int i = 0; i < 4; i++) wmma::fill_fragment(Cacc[i], 0.f);

    stage(0, 0);
    CPA_COMMIT();
    for (int kc = 0; kc < 16; kc++) {
        __syncthreads();
        if (kc + 1 < 16) { stage((kc + 1) & 1, (kc + 1) * 32); CPA_COMMIT(); CPA_WAIT1(); }
        else CPA_WAIT0();
        __syncthreads();
        const char* bs = sm + (kc & 1) * QSTG;
        const __nv_bfloat16* wh = (const __nv_bfloat16*)bs;
        const __nv_bfloat16* wl = (const __nv_bfloat16*)(bs + QW_WL);
        const __nv_bfloat16* hh = (const __nv_bfloat16*)(bs + QW_HH);
        const __nv_bfloat16* hl = (const __nv_bfloat16*)(bs + QW_HL);
#pragma unroll
        for (int kk = 0; kk < 2; kk++) {
            wmma::fragment<wmma::matrix_a, 16, 16, 16, __nv_bfloat16, wmma::row_major> Ah, Al;
            wmma::load_matrix_sync(Ah, wh + (osub * 16) * QLDW + kk * 16, QLDW);
            wmma::load_matrix_sync(Al, wl + (osub * 16) * QLDW + kk * 16, QLDW);
#pragma unroll
            for (int jn = 0; jn < 4; jn++) {
                wmma::fragment<wmma::matrix_b, 16, 16, 16, __nv_bfloat16, wmma::row_major> Bh, Bl;
                wmma::load_matrix_sync(Bh, hh + (kk * 16) * QLDH + ph * 64 + jn * 16, QLDH);
                wmma::load_matrix_sync(Bl, hl + (kk * 16) * QLDH + ph * 64 + jn * 16, QLDH);
                wmma::mma_sync(Cacc[jn], Ah, Bh, Cacc[jn]);
                wmma::mma_sync(Cacc[jn], Ah, Bl, Cacc[jn]);
                wmma::mma_sync(Cacc[jn], Al, Bh, Cacc[jn]);
            }
        }
    }
    __syncthreads();
    float* Es = (float*)sm;
#pragma unroll
    for (int jn = 0; jn < 4; jn++)
        wmma::store_matrix_sync(Es + (osub * 16) * QLDE + ph * 64 + jn * 16, Cacc[jn], QLDE, wmma::mem_row_major);
    __syncthreads();
    __nv_bfloat16* dh = (part == 0 ? g_qhi : part == 1 ? g_khi : g_vhi) + (size_t)bh * PP * 64;
    __nv_bfloat16* dl = (part == 0 ? g_qlo : part == 1 ? g_klo : g_vlo) + (size_t)bh * PP * 64;
    float scale = (part == 0) ? 0.125f : 1.0f;
    for (int idx = tid; idx < 2048; idx += 256) {
        int p = idx >> 4, d4 = (idx & 15) << 2;
        unsigned short hh[4], ll[4];
#pragma unroll
        for (int j = 0; j < 4; j++) {
            float v = Es[(d4 + j) * QLDE + p] * scale;
            __nv_bfloat16 h = __float2bfloat16_rn(v);
            hh[j] = bfu(h);
            ll[j] = bfu(__float2bfloat16_rn(v - __bfloat162float(h)));
        }
        size_t off = (size_t)(p0 + p) * 64 + d4;
        *(uint2*)(dh + off) = *(uint2*)hh;
        *(uint2*)(dl + off) = *(uint2*)ll;
    }
}

// ------------------------- SIMT proj GEMM ----------------------------------
__global__ __launch_bounds__(256) void gemm64(const float* __restrict__ W, const float* __restrict__ In,
        float* __restrict__ Out, const float* __restrict__ bias, const float* __restrict__ resid, int Mrows) {
    __shared__ float Ws[16][64];
    __shared__ float Hs[16][64];
    int tid = threadIdx.x, b = blockIdx.z;
    int o0 = blockIdx.y << 6, p0 = blockIdx.x << 6;
    const float* Wp = W + (size_t)o0 * CC;
    const float* Ip = In + (size_t)b * CC * PP + p0;
    int ty = tid >> 4, tx = tid & 15;
    int wrow = tid >> 2, wq = (tid & 3) << 2;
    int hk = tid >> 4, hq = (tid & 15) << 2;
    float acc[4][4] = {};
    for (int k0 = 0; k0 < CC; k0 += 16) {
        __syncthreads();
        float4 w4 = *(const float4*)(Wp + (size_t)wrow * CC + k0 + wq);
        Ws[wq][wrow] = w4.x; Ws[wq + 1][wrow] = w4.y; Ws[wq + 2][wrow] = w4.z; Ws[wq + 3][wrow] = w4.w;
        *(float4*)&Hs[hk][hq] = *(const float4*)(Ip + (size_t)(k0 + hk) * PP + hq);
        __syncthreads();
#pragma unroll
        for (int kk = 0; kk < 16; kk++) {
            float4 a = *(float4*)&Ws[kk][ty << 2];
            float4 h = *(float4*)&Hs[kk][tx << 2];
            const float *af = (const float*)&a, *hf = (const float*)&h;
#pragma unroll
            for (int r = 0; r < 4; r++)
#pragma unroll
                for (int u = 0; u < 4; u++) acc[r][u] += af[r] * hf[u];
        }
    }
#pragma unroll
    for (int r = 0; r < 4; r++) {
        int o = o0 + (ty << 2) + r;
        float bv = bias ? bias[o] : 0.f;
        size_t off = ((size_t)b * Mrows + o) * PP + p0 + (tx << 2);
        float4 v = make_float4(acc[r][0] + bv, acc[r][1] + bv, acc[r][2] + bv, acc[r][3] + bv);
        if (resid) { float4 rr = *(const float4*)(resid + off); v.x += rr.x; v.y += rr.y; v.z += rr.z; v.w += rr.w; }
        *(float4*)(Out + off) = v;
    }
}

// --------- attention: raw mma.m16n8k16, register-resident P ---------------
// smem: Qh 0 (36864) | Ql 36864 | KV 73728 + (t&1)*36864 | Ls 147456
// KV buffer: Kh +0, Kl +9216, Vh +18432, Vl +27648   (rows 144B, LDT=72)
#define AKV0 73728
#define AKVB 36864
#define ALS  147456
#define ATTN_SMEM 148480

__device__ __forceinline__ void load_kv4(uint32_t base,
        const __nv_bfloat16* kh, const __nv_bfloat16* kl,
        const __nv_bfloat16* vh, const __nv_bfloat16* vl, int j0, int tid) {
    for (int idx = tid; idx < 2048; idx += 512) {
        int m = idx >> 9, r = (idx >> 3) & 63, c8 = idx & 7;
        uint32_t d = base + m * 9216 + r * 144 + c8 * 16;
        const __nv_bfloat16* s = (m == 0 ? kh : m == 1 ? kl : m == 2 ? vh : vl) + (size_t)(j0 + r) * 64 + c8 * 8;
        cpa16(d, s);
    }
}

__global__ __launch_bounds__(512) void attn_mma(float* __restrict__ att) {
    extern __shared__ char sm[];
    uint32_t sb = smem_u32(sm);
    int tid = threadIdx.x, w = tid >> 5, lane = tid & 31;
    int bh = blockIdx.y, b = bh >> 3, nh = bh & 7;
    int i0 = blockIdx.x << 8;

    const __nv_bfloat16* qh = g_qhi + ((size_t)bh * PP + i0) * 64;
    const __nv_bfloat16* ql = g_qlo + ((size_t)bh * PP + i0) * 64;
    const __nv_bfloat16* kh = g_khi + (size_t)bh * PP * 64;
    const __nv_bfloat16* kl = g_klo + (size_t)bh * PP * 64;
    const __nv_bfloat16* vh = g_vhi + (size_t)bh * PP * 64;
    const __nv_bfloat16* vl = g_vlo + (size_t)bh * PP * 64;

    // stage Q planes (persistent) + first KV tile
    for (int idx = tid; idx < 4096; idx += 512) {
        int m = idx >> 11, r = (idx >> 3) & 255, c8 = idx & 7;
        uint32_t d = sb + m * 36864 + r * 144 + c8 * 16;
        const __nv_bfloat16* s = (m ? ql : qh) + (size_t)r * 64 + c8 * 8;
        cpa16(d, s);
    }
    load_kv4(sb + AKV0, kh, kl, vh, vl, 0, tid);
    CPA_COMMIT();

    float O[8][4];
#pragma unroll
    for (int i = 0; i < 8; i++)
#pragma unroll
        for (int j = 0; j < 4; j++) O[i][j] = 0.f;
    float lsum0 = 0.f, lsum1 = 0.f;

    uint32_t lrow = (lane & 7) + ((lane >> 3) & 1) * 8;
    uint32_t lc16 = (uint32_t)(lane >> 4) * 16;  // byte offset of col block
    uint32_t qrow = (uint32_t)(w * 16 + lrow) * 144 + lc16;

    for (int t = 0; t < 64; t++) {
        __syncthreads();
        if (t + 1 < 64) {
            load_kv4(sb + AKV0 + ((t + 1) & 1) * AKVB, kh, kl, vh, vl, (t + 1) * 64, tid);
            CPA_COMMIT(); CPA_WAIT1();
        } else CPA_WAIT0();
        __syncthreads();
        uint32_t kb = sb + AKV0 + (t & 1) * AKVB;

        // ---- S = QK^T (3-term) ----
        float S[8][4];
#pragma unroll
        for (int i = 0; i < 8; i++)
#pragma unroll
            for (int j = 0; j < 4; j++) S[i][j] = 0.f;
#pragma unroll
        for (int s = 0; s < 4; s++) {
            uint32_t qh4[4], ql4[4], k4[4];
            ldsm4(qh4, sb + qrow + s * 32);
            ldsm4(ql4, sb + 36864 + qrow + s * 32);
#pragma unroll
            for (int g = 0; g < 4; g++) {
                uint32_t krow = kb + (uint32_t)(g * 16 + lrow) * 144 + s * 32 + lc16;
                ldsm4(k4, krow);
                mma16816(S[2 * g], qh4, k4[0], k4[2]); mma16816(S[2 * g + 1], qh4, k4[1], k4[3]);
                mma16816(S[2 * g], ql4, k4[0], k4[2]); mma16816(S[2 * g + 1], ql4, k4[1], k4[3]);
                ldsm4(k4, krow + 9216);
                mma16816(S[2 * g], qh4, k4[0], k4[2]); mma16816(S[2 * g + 1], qh4, k4[1], k4[3]);
            }
        }

        // ---- exp + hi/lo split into A-fragments (registers only) ----
        uint32_t Ph[4][4], Pl[4][4];
#pragma unroll
        for (int t8 = 0; t8 < 8; t8++) {
            float e0 = __expf(S[t8][0]), e1 = __expf(S[t8][1]);
            float e2 = __expf(S[t8][2]), e3 = __expf(S[t8][3]);
            lsum0 += e0 + e1; lsum1 += e2 + e3;
            __nv_bfloat16 h0 = __float2bfloat16_rn(e0), h1 = __float2bfloat16_rn(e1);
            __nv_bfloat16 h2 = __float2bfloat16_rn(e2), h3 = __float2bfloat16_rn(e3);
            int s = t8 >> 1, o = (t8 & 1) * 2;
            Ph[s][o] = (uint32_t)bfu(h0) | ((uint32_t)bfu(h1) << 16);
            Ph[s][o + 1] = (uint32_t)bfu(h2) | ((uint32_t)bfu(h3) << 16);
            Pl[s][o] = pack2(e0 - __bfloat162float(h0), e1 - __bfloat162float(h1));
            Pl[s][o + 1] = pack2(e2 - __bfloat162float(h2), e3 - __bfloat162float(h3));
        }

        // ---- O += P V (3-term) ----
#pragma unroll
        for (int s = 0; s < 4; s++) {
            uint32_t v4[4];
#pragma unroll
            for (int g = 0; g < 4; g++) {
                uint32_t vrow = kb + 18432 + (uint32_t)(s * 16 + lrow) * 144 + g * 32 + lc16;
                ldsm4t(v4, vrow);
                mma16816(O[2 * g], Ph[s], v4[0], v4[1]); mma16816(O[2 * g + 1], Ph[s], v4[2], v4[3]);
                mma16816(O[2 * g], Pl[s], v4[0], v4[1]); mma16816(O[2 * g + 1], Pl[s], v4[2], v4[3]);
                ldsm4t(v4, vrow + 9216);
                mma16816(O[2 * g], Ph[s], v4[0], v4[1]); mma16816(O[2 * g + 1], Ph[s], v4[2], v4[3]);
            }
        }
    }

    // ---- finalize ----
    float* Ls = (float*)(sm + ALS);
    lsum0 += __shfl_xor_sync(0xffffffffu, lsum0, 1);
    lsum0 += __shfl_xor_sync(0xffffffffu, lsum0, 2);
    lsum1 += __shfl_xor_sync(0xffffffffu, lsum1, 1);
    lsum1 += __shfl_xor_sync(0xffffffffu, lsum1, 2);
    int r0 = w * 16 + (lane >> 2);
    if ((lane & 3) == 0) { Ls[r0] = lsum0; Ls[r0 + 8] = lsum1; }
    __syncthreads();
    float inv0 = 1.f / Ls[r0], inv1 = 1.f / Ls[r0 + 8];
    float* Ss = (float*)sm;  // reuse Q planes: 256 x 68 f32
    int cb = 2 * (lane & 3);
#pragma unroll
    for (int t8 = 0; t8 < 8; t8++) {
        int c = t8 * 8 + cb;
        Ss[r0 * 68 + c] = O[t8][0] * inv0;
        Ss[r0 * 68 + c + 1] = O[t8][1] * inv0;
        Ss[(r0 + 8) * 68 + c] = O[t8][2] * inv1;
        Ss[(r0 + 8) * 68 + c + 1] = O[t8][3] * inv1;
    }
    __syncthreads();
    float* ab = att + ((size_t)b * CC + nh * 64) * PP + i0;
    for (int idx = tid; idx < 4096; idx += 512) {
        int d = idx >> 6, i4 = (idx & 63) << 2;
        float4 o;
        o.x = Ss[(i4 + 0) * 68 + d];
        o.y = Ss[(i4 + 1) * 68 + d];
        o.z = Ss[(i4 + 2) * 68 + d];
        o.w = Ss[(i4 + 3) * 68 + d];
        *(float4*)(ab + (size_t)d * PP + i4) = o;
    }
}

// ---------------------------------------------------------------------------
extern "C" void kernel_launch(void* const* d_in, const int* in_sizes, int n_in,
                              void* d_out, int out_size) {
    const float* x = (const float*)d_in[0];
    const float* qkv_w = (const float*)d_in[1];
    const float* proj_w = (const float*)d_in[2];
    const float* proj_b = (const float*)d_in[3];
    const float* gn_w = (const float*)d_in[4];
    const float* gn_b = (const float*)d_in[5];
    float* out = (float*)d_out;

    float* attp;
    cudaGetSymbolAddress((void**)&attp, g_att);

    cudaFuncSetAttribute(qkv_wmma, cudaFuncAttributeMaxDynamicSharedMemorySize, QKV_SMEM);
    cudaFuncSetAttribute(attn_mma, cudaFuncAttributeMaxDynamicSharedMemorySize, ATTN_SMEM);

    gn_kernel<<<BB * GG, 256>>>(x, gn_w, gn_b);
    wsplit_kernel<<<768, 256>>>(qkv_w);
    qkv_wmma<<<dim3(PP / 128, 24, BB), 256, QKV_SMEM>>>(nullptr);
    attn_mma<<<dim3(PP / 256, NBH), 512, ATTN_SMEM>>>(attp);
    gemm64<<<dim3(PP / 64, CC / 64, BB), 256>>>(proj_w, attp, out, proj_b, x, CC);
}

// round 10
// speedup vs baseline: 4.5448x; 1.1876x over previous
#include <cuda_runtime.h>
#include <cuda_bf16.h>
#include <mma.h>
#include <math.h>
#include <stdint.h>
using namespace nvcuda;

#define BB 2
#define CC 512
#define PP 4096
#define NBH 16
#define GG 32
#define CPG 16
#define EPSV 1e-5f

__device__ __align__(16) __nv_bfloat16 g_hhi[BB * CC * PP];
__device__ __align__(16) __nv_bfloat16 g_hlo[BB * CC * PP];
__device__ __align__(16) __nv_bfloat16 g_wqh[3 * CC * CC];
__device__ __align__(16) __nv_bfloat16 g_wql[3 * CC * CC];
__device__ __align__(16) __nv_bfloat16 g_wph[CC * CC];
__device__ __align__(16) __nv_bfloat16 g_wpl[CC * CC];
__device__ __align__(16) __nv_bfloat16 g_qhi[NBH * PP * 64];
__device__ __align__(16) __nv_bfloat16 g_qlo[NBH * PP * 64];
__device__ __align__(16) __nv_bfloat16 g_khi[NBH * PP * 64];
__device__ __align__(16) __nv_bfloat16 g_klo[NBH * PP * 64];
__device__ __align__(16) __nv_bfloat16 g_vhi[NBH * PP * 64];
__device__ __align__(16) __nv_bfloat16 g_vlo[NBH * PP * 64];
__device__ __align__(16) __nv_bfloat16 g_athi[BB * CC * PP];
__device__ __align__(16) __nv_bfloat16 g_atlo[BB * CC * PP];

__device__ __forceinline__ uint32_t smem_u32(const void* p) {
    uint32_t a;
    asm("{ .reg .u64 t; cvta.to.shared.u64 t, %1; cvt.u32.u64 %0, t; }" : "=r"(a) : "l"(p));
    return a;
}
__device__ __forceinline__ void cpa16(uint32_t dst, const void* src) {
    asm volatile("cp.async.cg.shared.global [%0], [%1], 16;" :: "r"(dst), "l"(src));
}
#define CPA_COMMIT() asm volatile("cp.async.commit_group;" ::: "memory")
#define CPA_WAIT1()  asm volatile("cp.async.wait_group 1;" ::: "memory")
#define CPA_WAIT0()  asm volatile("cp.async.wait_group 0;" ::: "memory")
__device__ __forceinline__ unsigned short bfu(__nv_bfloat16 x) { return *(unsigned short*)&x; }
// pack two floats to bf16x2: low half = a, high half = b
__device__ __forceinline__ uint32_t cvt2(float a, float b) {
    uint32_t r;
    asm("cvt.rn.bf16x2.f32 %0, %1, %2;" : "=r"(r) : "f"(b), "f"(a));
    return r;
}
__device__ __forceinline__ void ldsm4(uint32_t* r, uint32_t a) {
    asm volatile("ldmatrix.sync.aligned.m8n8.x4.shared.b16 {%0,%1,%2,%3}, [%4];"
        : "=r"(r[0]), "=r"(r[1]), "=r"(r[2]), "=r"(r[3]) : "r"(a));
}
__device__ __forceinline__ void ldsm4t(uint32_t* r, uint32_t a) {
    asm volatile("ldmatrix.sync.aligned.m8n8.x4.trans.shared.b16 {%0,%1,%2,%3}, [%4];"
        : "=r"(r[0]), "=r"(r[1]), "=r"(r[2]), "=r"(r[3]) : "r"(a));
}
__device__ __forceinline__ void mma16816(float* c, const uint32_t* a, uint32_t b0, uint32_t b1) {
    asm volatile("mma.sync.aligned.m16n8k16.row.col.f32.bf16.bf16.f32 "
        "{%0,%1,%2,%3}, {%4,%5,%6,%7}, {%8,%9}, {%0,%1,%2,%3};"
        : "+f"(c[0]), "+f"(c[1]), "+f"(c[2]), "+f"(c[3])
        : "r"(a[0]), "r"(a[1]), "r"(a[2]), "r"(a[3]), "r"(b0), "r"(b1));
}

// --------- GroupNorm -> bf16 hi/lo ----------------------------------------
__global__ __launch_bounds__(256) void gn_kernel(const float* __restrict__ x,
        const float* __restrict__ gw, const float* __restrict__ gb) {
    int b = blockIdx.x / GG, g = blockIdx.x % GG;
    size_t base = ((size_t)b * CC + g * CPG) * PP;
    const float4* xp = (const float4*)(x + base);
    const int N4 = CPG * PP / 4;
    float s = 0.f, s2 = 0.f;
    for (int i = threadIdx.x; i < N4; i += 256) {
        float4 v = xp[i];
        s += v.x + v.y + v.z + v.w;
        s2 += v.x * v.x + v.y * v.y + v.z * v.z + v.w * v.w;
    }
    __shared__ float rs[256], rs2[256];
    rs[threadIdx.x] = s; rs2[threadIdx.x] = s2;
    __syncthreads();
    for (int o = 128; o > 0; o >>= 1) {
        if (threadIdx.x < o) { rs[threadIdx.x] += rs[threadIdx.x + o]; rs2[threadIdx.x] += rs2[threadIdx.x + o]; }
        __syncthreads();
    }
    __shared__ float sm2[2];
    if (threadIdx.x == 0) {
        float mean = rs[0] / (float)(CPG * PP);
        sm2[0] = mean; sm2[1] = rsqrtf(rs2[0] / (float)(CPG * PP) - mean * mean + EPSV);
    }
    __syncthreads();
    float mean = sm2[0], rstd = sm2[1];
    for (int i = threadIdx.x; i < N4; i += 256) {
        int c = g * CPG + (i >> 10);
        float ga = gw[c] * rstd, be = gb[c];
        float4 v = xp[i];
        float v0 = (v.x - mean) * ga + be, v1 = (v.y - mean) * ga + be;
        float v2 = (v.z - mean) * ga + be, v3 = (v.w - mean) * ga + be;
        uint32_t h01 = cvt2(v0, v1), h23 = cvt2(v2, v3);
        float f0 = __uint_as_float(h01 << 16), f1 = __uint_as_float(h01 & 0xffff0000u);
        float f2 = __uint_as_float(h23 << 16), f3 = __uint_as_float(h23 & 0xffff0000u);
        uint2 hh; hh.x = h01; hh.y = h23;
        uint2 ll; ll.x = cvt2(v0 - f0, v1 - f1); ll.y = cvt2(v2 - f2, v3 - f3);
        *(uint2*)(g_hhi + base + i * 4) = hh;
        *(uint2*)(g_hlo + base + i * 4) = ll;
    }
}

// --------- split weights into bf16 hi/lo ----------------------------------
__global__ __launch_bounds__(256) void wsplit_kernel(const float* __restrict__ w,
        __nv_bfloat16* __restrict__ dh, __nv_bfloat16* __restrict__ dl, int n) {
    for (int i = blockIdx.x * 256 + threadIdx.x; i < n; i += gridDim.x * 256) {
        float v = w[i];
        __nv_bfloat16 h = __float2bfloat16_rn(v);
        dh[i] = h;
        dl[i] = __float2bfloat16_rn(v - __bfloat162float(h));
    }
}

// --------- QKV GEMM (wmma hi/lo) + fused split/transpose epilogue ---------
#define QLDW 40
#define QLDH 136
#define QSTG 27648
#define QW_WL 5120
#define QW_HH 10240
#define QW_HL 18944
#define QLDE 132
#define QKV_SMEM (2 * QSTG)

__global__ __launch_bounds__(256) void qkv_wmma() {
    extern __shared__ char sm[];
    uint32_t sb = smem_u32(sm);
    int tid = threadIdx.x, w = tid >> 5;
    int p0 = blockIdx.x << 7;
    int nh = blockIdx.y / 3, part = blockIdx.y % 3;
    int o0 = blockIdx.y << 6;
    int b = blockIdx.z, bh = b * 8 + nh;
    int osub = w >> 1, ph = w & 1;

    const __nv_bfloat16* Wh = g_wqh + (size_t)o0 * CC;
    const __nv_bfloat16* Wl = g_wql + (size_t)o0 * CC;
    const __nv_bfloat16* Hh = g_hhi + (size_t)b * CC * PP;
    const __nv_bfloat16* Hl = g_hlo + (size_t)b * CC * PP;

    auto stage = [&](int buf, int k0) {
        uint32_t bs = sb + buf * QSTG;
        for (int idx = tid; idx < 512; idx += 256) {
            int m = idx >> 8, r = (idx >> 2) & 63, c8 = idx & 3;
            cpa16(bs + m * QW_WL + r * 80 + c8 * 16, (m ? Wl : Wh) + (size_t)r * CC + k0 + c8 * 8);
        }
        for (int idx = tid; idx < 1024; idx += 256) {
            int m = idx >> 9, r = (idx >> 4) & 31, c8 = idx & 15;
            cpa16(bs + QW_HH + m * 8704 + r * 272 + c8 * 16, (m ? Hl : Hh) + (size_t)(k0 + r) * PP + p0 + c8 * 8);
        }
    };

    wmma::fragment<wmma::accumulator, 16, 16, 16, float> Cacc[4];
#pragma unroll
    for (int i = 0; i < 4; i++) wmma::fill_fragment(Cacc[i], 0.f);

    stage(0, 0);
    CPA_COMMIT();
    for (int kc = 0; kc < 16; kc++) {
        __syncthreads();
        if (kc + 1 < 16) { stage((kc + 1) & 1, (kc + 1) * 32); CPA_COMMIT(); CPA_WAIT1(); }
        else CPA_WAIT0();
        __syncthreads();
        const char* bs = sm + (kc & 1) * QSTG;
        const __nv_bfloat16* wh = (const __nv_bfloat16*)bs;
        const __nv_bfloat16* wl = (const __nv_bfloat16*)(bs + QW_WL);
        const __nv_bfloat16* hh = (const __nv_bfloat16*)(bs + QW_HH);
        const __nv_bfloat16* hl = (const __nv_bfloat16*)(bs + QW_HL);
#pragma unroll
        for (int kk = 0; kk < 2; kk++) {
            wmma::fragment<wmma::matrix_a, 16, 16, 16, __nv_bfloat16, wmma::row_major> Ah, Al;
            wmma::load_matrix_sync(Ah, wh + (osub * 16) * QLDW + kk * 16, QLDW);
            wmma::load_matrix_sync(Al, wl + (osub * 16) * QLDW + kk * 16, QLDW);
#pragma unroll
            for (int jn = 0; jn < 4; jn++) {
                wmma::fragment<wmma::matrix_b, 16, 16, 16, __nv_bfloat16, wmma::row_major> Bh, Bl;
                wmma::load_matrix_sync(Bh, hh + (kk * 16) * QLDH + ph * 64 + jn * 16, QLDH);
                wmma::load_matrix_sync(Bl, hl + (kk * 16) * QLDH + ph * 64 + jn * 16, QLDH);
                wmma::mma_sync(Cacc[jn], Ah, Bh, Cacc[jn]);
                wmma::mma_sync(Cacc[jn], Ah, Bl, Cacc[jn]);
                wmma::mma_sync(Cacc[jn], Al, Bh, Cacc[jn]);
            }
        }
    }
    __syncthreads();
    float* Es = (float*)sm;
#pragma unroll
    for (int jn = 0; jn < 4; jn++)
        wmma::store_matrix_sync(Es + (osub * 16) * QLDE + ph * 64 + jn * 16, Cacc[jn], QLDE, wmma::mem_row_major);
    __syncthreads();
    __nv_bfloat16* dh = (part == 0 ? g_qhi : part == 1 ? g_khi : g_vhi) + (size_t)bh * PP * 64;
    __nv_bfloat16* dl = (part == 0 ? g_qlo : part == 1 ? g_klo : g_vlo) + (size_t)bh * PP * 64;
    float scale = (part == 0) ? 0.125f : 1.0f;
    for (int idx = tid; idx < 2048; idx += 256) {
        int p = idx >> 4, d4 = (idx & 15) << 2;
        float v0 = Es[(d4 + 0) * QLDE + p] * scale, v1 = Es[(d4 + 1) * QLDE + p] * scale;
        float v2 = Es[(d4 + 2) * QLDE + p] * scale, v3 = Es[(d4 + 3) * QLDE + p] * scale;
        uint32_t h01 = cvt2(v0, v1), h23 = cvt2(v2, v3);
        float f0 = __uint_as_float(h01 << 16), f1 = __uint_as_float(h01 & 0xffff0000u);
        float f2 = __uint_as_float(h23 << 16), f3 = __uint_as_float(h23 & 0xffff0000u);
        uint2 hh; hh.x = h01; hh.y = h23;
        uint2 ll; ll.x = cvt2(v0 - f0, v1 - f1); ll.y = cvt2(v2 - f2, v3 - f3);
        size_t off = (size_t)(p0 + p) * 64 + d4;
        *(uint2*)(dh + off) = hh;
        *(uint2*)(dl + off) = ll;
    }
}

// --------- proj GEMM (wmma hi/lo) + bias + residual ------------------------
__global__ __launch_bounds__(256) void proj_wmma(const float* __restrict__ bias,
        const float* __restrict__ xin, float* __restrict__ out) {
    extern __shared__ char sm[];
    uint32_t sb = smem_u32(sm);
    int tid = threadIdx.x, w = tid >> 5;
    int p0 = blockIdx.x << 7;
    int o0 = blockIdx.y << 6;
    int b = blockIdx.z;
    int osub = w >> 1, ph = w & 1;

    const __nv_bfloat16* Wh = g_wph + (size_t)o0 * CC;
    const __nv_bfloat16* Wl = g_wpl + (size_t)o0 * CC;
    const __nv_bfloat16* Hh = g_athi + (size_t)b * CC * PP;
    const __nv_bfloat16* Hl = g_atlo + (size_t)b * CC * PP;

    auto stage = [&](int buf, int k0) {
        uint32_t bs = sb + buf * QSTG;
        for (int idx = tid; idx < 512; idx += 256) {
            int m = idx >> 8, r = (idx >> 2) & 63, c8 = idx & 3;
            cpa16(bs + m * QW_WL + r * 80 + c8 * 16, (m ? Wl : Wh) + (size_t)r * CC + k0 + c8 * 8);
        }
        for (int idx = tid; idx < 1024; idx += 256) {
            int m = idx >> 9, r = (idx >> 4) & 31, c8 = idx & 15;
            cpa16(bs + QW_HH + m * 8704 + r * 272 + c8 * 16, (m ? Hl : Hh) + (size_t)(k0 + r) * PP + p0 + c8 * 8);
        }
    };

    wmma::fragment<wmma::accumulator, 16, 16, 16, float> Cacc[4];
#pragma unroll
    for (int i = 0; i < 4; i++) wmma::fill_fragment(Cacc[i], 0.f);

    stage(0, 0);
    CPA_COMMIT();
    for (int kc = 0; kc < 16; kc++) {
        __syncthreads();
        if (kc + 1 < 16) { stage((kc + 1) & 1, (kc + 1) * 32); CPA_COMMIT(); CPA_WAIT1(); }
        else CPA_WAIT0();
        __syncthreads();
        const char* bs = sm + (kc & 1) * QSTG;
        const __nv_bfloat16* wh = (const __nv_bfloat16*)bs;
        const __nv_bfloat16* wl = (const __nv_bfloat16*)(bs + QW_WL);
        const __nv_bfloat16* hh = (const __nv_bfloat16*)(bs + QW_HH);
        const __nv_bfloat16* hl = (const __nv_bfloat16*)(bs + QW_HL);
#pragma unroll
        for (int kk = 0; kk < 2; kk++) {
            wmma::fragment<wmma::matrix_a, 16, 16, 16, __nv_bfloat16, wmma::row_major> Ah, Al;
            wmma::load_matrix_sync(Ah, wh + (osub * 16) * QLDW + kk * 16, QLDW);
            wmma::load_matrix_sync(Al, wl + (osub * 16) * QLDW + kk * 16, QLDW);
#pragma unroll
            for (int jn = 0; jn < 4; jn++) {
                wmma::fragment<wmma::matrix_b, 16, 16, 16, __nv_bfloat16, wmma::row_major> Bh, Bl;
                wmma::load_matrix_sync(Bh, hh + (kk * 16) * QLDH + ph * 64 + jn * 16, QLDH);
                wmma::load_matrix_sync(Bl, hl + (kk * 16) * QLDH + ph * 64 + jn * 16, QLDH);
                wmma::mma_sync(Cacc[jn], Ah, Bh, Cacc[jn]);
                wmma::mma_sync(Cacc[jn], Ah, Bl, Cacc[jn]);
                wmma::mma_sync(Cacc[jn], Al, Bh, Cacc[jn]);
            }
        }
    }
    __syncthreads();
    float* Es = (float*)sm;
#pragma unroll
    for (int jn = 0; jn < 4; jn++)
        wmma::store_matrix_sync(Es + (osub * 16) * QLDE + ph * 64 + jn * 16, Cacc[jn], QLDE, wmma::mem_row_major);
    __syncthreads();
    for (int idx = tid; idx < 2048; idx += 256) {
        int o = idx >> 5, p4 = (idx & 31) << 2;
        float4 v = *(float4*)&Es[o * QLDE + p4];
        float bv = bias[o0 + o];
        size_t off = ((size_t)b * CC + o0 + o) * PP + p0 + p4;
        float4 xr = *(const float4*)(xin + off);
        v.x += bv + xr.x; v.y += bv + xr.y; v.z += bv + xr.z; v.w += bv + xr.w;
        *(float4*)(out + off) = v;
    }
}

// --------- attention: raw mma, 256 threads, 2 CTAs/SM ----------------------
// smem: Qh 0 (18432) | Ql 18432 | KV 36864 + (t&1)*36864 | Ls 110592
#define AQL  18432
#define AKV0 36864
#define AKVB 36864
#define ALS  110592
#define ATTN_SMEM 111104

__device__ __forceinline__ void load_kv4(uint32_t base,
        const __nv_bfloat16* kh, const __nv_bfloat16* kl,
        const __nv_bfloat16* vh, const __nv_bfloat16* vl, int j0, int tid) {
    for (int idx = tid; idx < 2048; idx += 256) {
        int m = idx >> 9, r = (idx >> 3) & 63, c8 = idx & 7;
        uint32_t d = base + m * 9216 + r * 144 + c8 * 16;
        const __nv_bfloat16* s = (m == 0 ? kh : m == 1 ? kl : m == 2 ? vh : vl) + (size_t)(j0 + r) * 64 + c8 * 8;
        cpa16(d, s);
    }
}

__global__ __launch_bounds__(256, 2) void attn_mma() {
    extern __shared__ char sm[];
    uint32_t sb = smem_u32(sm);
    int tid = threadIdx.x, w = tid >> 5, lane = tid & 31;
    int bh = blockIdx.y, b = bh >> 3, nh = bh & 7;
    int i0 = blockIdx.x << 7;  // 128-row q tile

    const __nv_bfloat16* qh = g_qhi + ((size_t)bh * PP + i0) * 64;
    const __nv_bfloat16* ql = g_qlo + ((size_t)bh * PP + i0) * 64;
    const __nv_bfloat16* kh = g_khi + (size_t)bh * PP * 64;
    const __nv_bfloat16* kl = g_klo + (size_t)bh * PP * 64;
    const __nv_bfloat16* vh = g_vhi + (size_t)bh * PP * 64;
    const __nv_bfloat16* vl = g_vlo + (size_t)bh * PP * 64;

    for (int idx = tid; idx < 2048; idx += 256) {
        int m = idx >> 10, r = (idx >> 3) & 127, c8 = idx & 7;
        uint32_t d = sb + m * AQL + r * 144 + c8 * 16;
        cpa16(d, (m ? ql : qh) + (size_t)r * 64 + c8 * 8);
    }
    load_kv4(sb + AKV0, kh, kl, vh, vl, 0, tid);
    CPA_COMMIT();

    float O[8][4];
#pragma unroll
    for (int i = 0; i < 8; i++)
#pragma unroll
        for (int j = 0; j < 4; j++) O[i][j] = 0.f;
    float lsum0 = 0.f, lsum1 = 0.f;

    uint32_t lrow = (lane & 7) + ((lane >> 3) & 1) * 8;
    uint32_t lc16 = (uint32_t)(lane >> 4) * 16;
    uint32_t qrow = (uint32_t)(w * 16 + lrow) * 144 + lc16;

    for (int t = 0; t < 64; t++) {
        __syncthreads();
        if (t + 1 < 64) {
            load_kv4(sb + AKV0 + ((t + 1) & 1) * AKVB, kh, kl, vh, vl, (t + 1) * 64, tid);
            CPA_COMMIT(); CPA_WAIT1();
        } else CPA_WAIT0();
        __syncthreads();
        uint32_t kb = sb + AKV0 + (t & 1) * AKVB;

        float S[8][4];
#pragma unroll
        for (int i = 0; i < 8; i++)
#pragma unroll
            for (int j = 0; j < 4; j++) S[i][j] = 0.f;
#pragma unroll
        for (int s = 0; s < 4; s++) {
            uint32_t qh4[4], ql4[4], k4[4];
            ldsm4(qh4, sb + qrow + s * 32);
            ldsm4(ql4, sb + AQL + qrow + s * 32);
#pragma unroll
            for (int g = 0; g < 4; g++) {
                uint32_t krow = kb + (uint32_t)(g * 16 + lrow) * 144 + s * 32 + lc16;
                ldsm4(k4, krow);
                mma16816(S[2 * g], qh4, k4[0], k4[2]); mma16816(S[2 * g + 1], qh4, k4[1], k4[3]);
                mma16816(S[2 * g], ql4, k4[0], k4[2]); mma16816(S[2 * g + 1], ql4, k4[1], k4[3]);
                ldsm4(k4, krow + 9216);
                mma16816(S[2 * g], qh4, k4[0], k4[2]); mma16816(S[2 * g + 1], qh4, k4[1], k4[3]);
            }
        }

        uint32_t Ph[4][4], Pl[4][4];
#pragma unroll
        for (int t8 = 0; t8 < 8; t8++) {
            float e0 = __expf(S[t8][0]), e1 = __expf(S[t8][1]);
            float e2 = __expf(S[t8][2]), e3 = __expf(S[t8][3]);
            lsum0 += e0 + e1; lsum1 += e2 + e3;
            int s = t8 >> 1, o = (t8 & 1) * 2;
            uint32_t h01 = cvt2(e0, e1), h23 = cvt2(e2, e3);
            Ph[s][o] = h01; Ph[s][o + 1] = h23;
            float f0 = __uint_as_float(h01 << 16), f1 = __uint_as_float(h01 & 0xffff0000u);
            float f2 = __uint_as_float(h23 << 16), f3 = __uint_as_float(h23 & 0xffff0000u);
            Pl[s][o] = cvt2(e0 - f0, e1 - f1);
            Pl[s][o + 1] = cvt2(e2 - f2, e3 - f3);
        }

#pragma unroll
        for (int s = 0; s < 4; s++) {
            uint32_t v4[4];
#pragma unroll
            for (int g = 0; g < 4; g++) {
                uint32_t vrow = kb + 18432 + (uint32_t)(s * 16 + lrow) * 144 + g * 32 + lc16;
                ldsm4t(v4, vrow);
                mma16816(O[2 * g], Ph[s], v4[0], v4[1]); mma16816(O[2 * g + 1], Ph[s], v4[2], v4[3]);
                mma16816(O[2 * g], Pl[s], v4[0], v4[1]); mma16816(O[2 * g + 1], Pl[s], v4[2], v4[3]);
                ldsm4t(v4, vrow + 9216);
                mma16816(O[2 * g], Ph[s], v4[0], v4[1]); mma16816(O[2 * g + 1], Ph[s], v4[2], v4[3]);
            }
        }
    }

    float* Ls = (float*)(sm + ALS);
    lsum0 += __shfl_xor_sync(0xffffffffu, lsum0, 1);
    lsum0 += __shfl_xor_sync(0xffffffffu, lsum0, 2);
    lsum1 += __shfl_xor_sync(0xffffffffu, lsum1, 1);
    lsum1 += __shfl_xor_sync(0xffffffffu, lsum1, 2);
    int r0 = w * 16 + (lane >> 2);
    if ((lane & 3) == 0) { Ls[r0] = lsum0; Ls[r0 + 8] = lsum1; }
    __syncthreads();
    float inv0 = 1.f / Ls[r0], inv1 = 1.f / Ls[r0 + 8];
    float* Ss = (float*)sm;  // reuse Q planes: 128 x 68 f32
    int cb = 2 * (lane & 3);
#pragma unroll
    for (int t8 = 0; t8 < 8; t8++) {
        int c = t8 * 8 + cb;
        Ss[r0 * 68 + c] = O[t8][0] * inv0;
        Ss[r0 * 68 + c + 1] = O[t8][1] * inv0;
        Ss[(r0 + 8) * 68 + c] = O[t8][2] * inv1;
        Ss[(r0 + 8) * 68 + c + 1] = O[t8][3] * inv1;
    }
    __syncthreads();
    __nv_bfloat16* ah = g_athi + ((size_t)b * CC + nh * 64) * PP + i0;
    __nv_bfloat16* al = g_atlo + ((size_t)b * CC + nh * 64) * PP + i0;
    for (int idx = tid; idx < 2048; idx += 256) {
        int d = idx >> 5, i4 = (idx & 31) << 2;
        float v0 = Ss[(i4 + 0) * 68 + d], v1 = Ss[(i4 + 1) * 68 + d];
        float v2 = Ss[(i4 + 2) * 68 + d], v3 = Ss[(i4 + 3) * 68 + d];
        uint32_t h01 = cvt2(v0, v1), h23 = cvt2(v2, v3);
        float f0 = __uint_as_float(h01 << 16), f1 = __uint_as_float(h01 & 0xffff0000u);
        float f2 = __uint_as_float(h23 << 16), f3 = __uint_as_float(h23 & 0xffff0000u);
        uint2 hh; hh.x = h01; hh.y = h23;
        uint2 ll; ll.x = cvt2(v0 - f0, v1 - f1); ll.y = cvt2(v2 - f2, v3 - f3);
        *(uint2*)(ah + (size_t)d * PP + i4) = hh;
        *(uint2*)(al + (size_t)d * PP + i4) = ll;
    }
}

// ---------------------------------------------------------------------------
extern "C" void kernel_launch(void* const* d_in, const int* in_sizes, int n_in,
                              void* d_out, int out_size) {
    const float* x = (const float*)d_in[0];
    const float* qkv_w = (const float*)d_in[1];
    const float* proj_w = (const float*)d_in[2];
    const float* proj_b = (const float*)d_in[3];
    const float* gn_w = (const float*)d_in[4];
    const float* gn_b = (const float*)d_in[5];
    float* out = (float*)d_out;

    __nv_bfloat16 *wqh, *wql, *wph, *wpl;
    cudaGetSymbolAddress((void**)&wqh, g_wqh);
    cudaGetSymbolAddress((void**)&wql, g_wql);
    cudaGetSymbolAddress((void**)&wph, g_wph);
    cudaGetSymbolAddress((void**)&wpl, g_wpl);

    cudaFuncSetAttribute(qkv_wmma, cudaFuncAttributeMaxDynamicSharedMemorySize, QKV_SMEM);
    cudaFuncSetAttribute(proj_wmma, cudaFuncAttributeMaxDynamicSharedMemorySize, QKV_SMEM);
    cudaFuncSetAttribute(attn_mma, cudaFuncAttributeMaxDynamicSharedMemorySize, ATTN_SMEM);

    gn_kernel<<<BB * GG, 256>>>(x, gn_w, gn_b);
    wsplit_kernel<<<512, 256>>>(qkv_w, wqh, wql, 3 * CC * CC);
    wsplit_kernel<<<256, 256>>>(proj_w, wph, wpl, CC * CC);
    qkv_wmma<<<dim3(PP / 128, 24, BB), 256, QKV_SMEM>>>();
    attn_mma<<<dim3(PP / 128, NBH), 256, ATTN_SMEM>>>();
    proj_wmma<<<dim3(PP / 128, CC / 64, BB), 256, QKV_SMEM>>>(proj_b, x, out);
}

// round 11
// speedup vs baseline: 11.1102x; 2.4446x over previous
#include <cuda_runtime.h>
#include <cuda_fp16.h>
#include <mma.h>
#include <math.h>
#include <stdint.h>
using namespace nvcuda;

#define BB 2
#define CC 512
#define PP 4096
#define NBH 16
#define GG 32
#define CPG 16
#define EPSV 1e-5f

__device__ __align__(16) __half g_h16[BB * CC * PP];
__device__ __align__(16) __half g_wq16[3 * CC * CC];
__device__ __align__(16) __half g_wp16[CC * CC];
__device__ __align__(16) __half g_q16[NBH * PP * 64];
__device__ __align__(16) __half g_k16[NBH * PP * 64];
__device__ __align__(16) __half g_v16[NBH * PP * 64];
__device__ __align__(16) __half g_at16[BB * CC * PP];

__device__ __forceinline__ uint32_t smem_u32(const void* p) {
    uint32_t a;
    asm("{ .reg .u64 t; cvta.to.shared.u64 t, %1; cvt.u32.u64 %0, t; }" : "=r"(a) : "l"(p));
    return a;
}
__device__ __forceinline__ void cpa16(uint32_t dst, const void* src) {
    asm volatile("cp.async.cg.shared.global [%0], [%1], 16;" :: "r"(dst), "l"(src));
}
#define CPA_COMMIT() asm volatile("cp.async.commit_group;" ::: "memory")
#define CPA_WAIT1()  asm volatile("cp.async.wait_group 1;" ::: "memory")
#define CPA_WAIT0()  asm volatile("cp.async.wait_group 0;" ::: "memory")
// pack two floats to f16x2: low half = a, high half = b
__device__ __forceinline__ uint32_t cvt2h(float a, float b) {
    uint32_t r;
    asm("cvt.rn.f16x2.f32 %0, %1, %2;" : "=r"(r) : "f"(b), "f"(a));
    return r;
}
__device__ __forceinline__ void ldsm4(uint32_t* r, uint32_t a) {
    asm volatile("ldmatrix.sync.aligned.m8n8.x4.shared.b16 {%0,%1,%2,%3}, [%4];"
        : "=r"(r[0]), "=r"(r[1]), "=r"(r[2]), "=r"(r[3]) : "r"(a));
}
__device__ __forceinline__ void ldsm4t(uint32_t* r, uint32_t a) {
    asm volatile("ldmatrix.sync.aligned.m8n8.x4.trans.shared.b16 {%0,%1,%2,%3}, [%4];"
        : "=r"(r[0]), "=r"(r[1]), "=r"(r[2]), "=r"(r[3]) : "r"(a));
}
__device__ __forceinline__ void mma16816h(float* c, const uint32_t* a, uint32_t b0, uint32_t b1) {
    asm volatile("mma.sync.aligned.m16n8k16.row.col.f32.f16.f16.f32 "
        "{%0,%1,%2,%3}, {%4,%5,%6,%7}, {%8,%9}, {%0,%1,%2,%3};"
        : "+f"(c[0]), "+f"(c[1]), "+f"(c[2]), "+f"(c[3])
        : "r"(a[0]), "r"(a[1]), "r"(a[2]), "r"(a[3]), "r"(b0), "r"(b1));
}

// --------- GroupNorm -> fp16 ------------------------------------------------
__global__ __launch_bounds__(256) void gn_kernel(const float* __restrict__ x,
        const float* __restrict__ gw, const float* __restrict__ gb) {
    int b = blockIdx.x / GG, g = blockIdx.x % GG;
    size_t base = ((size_t)b * CC + g * CPG) * PP;
    const float4* xp = (const float4*)(x + base);
    const int N4 = CPG * PP / 4;
    float s = 0.f, s2 = 0.f;
    for (int i = threadIdx.x; i < N4; i += 256) {
        float4 v = xp[i];
        s += v.x + v.y + v.z + v.w;
        s2 += v.x * v.x + v.y * v.y + v.z * v.z + v.w * v.w;
    }
    __shared__ float rs[256], rs2[256];
    rs[threadIdx.x] = s; rs2[threadIdx.x] = s2;
    __syncthreads();
    for (int o = 128; o > 0; o >>= 1) {
        if (threadIdx.x < o) { rs[threadIdx.x] += rs[threadIdx.x + o]; rs2[threadIdx.x] += rs2[threadIdx.x + o]; }
        __syncthreads();
    }
    __shared__ float sm2[2];
    if (threadIdx.x == 0) {
        float mean = rs[0] / (float)(CPG * PP);
        sm2[0] = mean; sm2[1] = rsqrtf(rs2[0] / (float)(CPG * PP) - mean * mean + EPSV);
    }
    __syncthreads();
    float mean = sm2[0], rstd = sm2[1];
    for (int i = threadIdx.x; i < N4; i += 256) {
        int c = g * CPG + (i >> 10);
        float ga = gw[c] * rstd, be = gb[c];
        float4 v = xp[i];
        uint2 hh;
        hh.x = cvt2h((v.x - mean) * ga + be, (v.y - mean) * ga + be);
        hh.y = cvt2h((v.z - mean) * ga + be, (v.w - mean) * ga + be);
        *(uint2*)(g_h16 + base + i * 4) = hh;
    }
}

// --------- convert weights fp32 -> fp16 -------------------------------------
__global__ __launch_bounds__(256) void wconv_kernel(const float* __restrict__ w,
        __half* __restrict__ dh, int n) {
    for (int i = blockIdx.x * 256 + threadIdx.x; i < n; i += gridDim.x * 256) {
        dh[i] = __float2half_rn(w[i]);
    }
}

// --------- QKV GEMM (fp16 wmma) + fused transpose epilogue ------------------
#define QLDW 40
#define QLDH 136
#define QSTG 13824       // W 64x80B (5120) + H 32x272B (8704)
#define QW_H 5120
#define QLDE 132
#define QKV_SMEM 34048   // epilogue Es 64x132 f32 = 33792 dominates

__global__ __launch_bounds__(256) void qkv_wmma() {
    extern __shared__ char sm[];
    uint32_t sb = smem_u32(sm);
    int tid = threadIdx.x, w = tid >> 5;
    int p0 = blockIdx.x << 7;
    int nh = blockIdx.y / 3, part = blockIdx.y % 3;
    int o0 = blockIdx.y << 6;
    int b = blockIdx.z, bh = b * 8 + nh;
    int osub = w >> 1, ph = w & 1;

    const __half* W = g_wq16 + (size_t)o0 * CC;
    const __half* H = g_h16 + (size_t)b * CC * PP;

    auto stage = [&](int buf, int k0) {
        uint32_t bs = sb + buf * QSTG;
        for (int idx = tid; idx < 256; idx += 256) {
            int r = idx >> 2, c8 = idx & 3;
            cpa16(bs + r * 80 + c8 * 16, W + (size_t)r * CC + k0 + c8 * 8);
        }
        for (int idx = tid; idx < 512; idx += 256) {
            int r = idx >> 4, c8 = idx & 15;
            cpa16(bs + QW_H + r * 272 + c8 * 16, H + (size_t)(k0 + r) * PP + p0 + c8 * 8);
        }
    };

    wmma::fragment<wmma::accumulator, 16, 16, 16, float> Cacc[4];
#pragma unroll
    for (int i = 0; i < 4; i++) wmma::fill_fragment(Cacc[i], 0.f);

    stage(0, 0);
    CPA_COMMIT();
    for (int kc = 0; kc < 16; kc++) {
        __syncthreads();
        if (kc + 1 < 16) { stage((kc + 1) & 1, (kc + 1) * 32); CPA_COMMIT(); CPA_WAIT1(); }
        else CPA_WAIT0();
        __syncthreads();
        const char* bs = sm + (kc & 1) * QSTG;
        const __half* wh = (const __half*)bs;
        const __half* hh = (const __half*)(bs + QW_H);
#pragma unroll
        for (int kk = 0; kk < 2; kk++) {
            wmma::fragment<wmma::matrix_a, 16, 16, 16, __half, wmma::row_major> Ah;
            wmma::load_matrix_sync(Ah, wh + (osub * 16) * QLDW + kk * 16, QLDW);
#pragma unroll
            for (int jn = 0; jn < 4; jn++) {
                wmma::fragment<wmma::matrix_b, 16, 16, 16, __half, wmma::row_major> Bh;
                wmma::load_matrix_sync(Bh, hh + (kk * 16) * QLDH + ph * 64 + jn * 16, QLDH);
                wmma::mma_sync(Cacc[jn], Ah, Bh, Cacc[jn]);
            }
        }
    }
    __syncthreads();
    float* Es = (float*)sm;
#pragma unroll
    for (int jn = 0; jn < 4; jn++)
        wmma::store_matrix_sync(Es + (osub * 16) * QLDE + ph * 64 + jn * 16, Cacc[jn], QLDE, wmma::mem_row_major);
    __syncthreads();
    __half* dh = (part == 0 ? g_q16 : part == 1 ? g_k16 : g_v16) + (size_t)bh * PP * 64;
    float scale = (part == 0) ? 0.125f : 1.0f;
    for (int idx = tid; idx < 2048; idx += 256) {
        int p = idx >> 4, d4 = (idx & 15) << 2;
        uint2 hh;
        hh.x = cvt2h(Es[(d4 + 0) * QLDE + p] * scale, Es[(d4 + 1) * QLDE + p] * scale);
        hh.y = cvt2h(Es[(d4 + 2) * QLDE + p] * scale, Es[(d4 + 3) * QLDE + p] * scale);
        *(uint2*)(dh + (size_t)(p0 + p) * 64 + d4) = hh;
    }
}

// --------- proj GEMM (fp16 wmma) + bias + residual --------------------------
__global__ __launch_bounds__(256) void proj_wmma(const float* __restrict__ bias,
        const float* __restrict__ xin, float* __restrict__ out) {
    extern __shared__ char sm[];
    uint32_t sb = smem_u32(sm);
    int tid = threadIdx.x, w = tid >> 5;
    int p0 = blockIdx.x << 7;
    int o0 = blockIdx.y << 6;
    int b = blockIdx.z;
    int osub = w >> 1, ph = w & 1;

    const __half* W = g_wp16 + (size_t)o0 * CC;
    const __half* H = g_at16 + (size_t)b * CC * PP;

    auto stage = [&](int buf, int k0) {
        uint32_t bs = sb + buf * QSTG;
        for (int idx = tid; idx < 256; idx += 256) {
            int r = idx >> 2, c8 = idx & 3;
            cpa16(bs + r * 80 + c8 * 16, W + (size_t)r * CC + k0 + c8 * 8);
        }
        for (int idx = tid; idx < 512; idx += 256) {
            int r = idx >> 4, c8 = idx & 15;
            cpa16(bs + QW_H + r * 272 + c8 * 16, H + (size_t)(k0 + r) * PP + p0 + c8 * 8);
        }
    };

    wmma::fragment<wmma::accumulator, 16, 16, 16, float> Cacc[4];
#pragma unroll
    for (int i = 0; i < 4; i++) wmma::fill_fragment(Cacc[i], 0.f);

    stage(0, 0);
    CPA_COMMIT();
    for (int kc = 0; kc < 16; kc++) {
        __syncthreads();
        if (kc + 1 < 16) { stage((kc + 1) & 1, (kc + 1) * 32); CPA_COMMIT(); CPA_WAIT1(); }
        else CPA_WAIT0();
        __syncthreads();
        const char* bs = sm + (kc & 1) * QSTG;
        const __half* wh = (const __half*)bs;
        const __half* hh = (const __half*)(bs + QW_H);
#pragma unroll
        for (int kk = 0; kk < 2; kk++) {
            wmma::fragment<wmma::matrix_a, 16, 16, 16, __half, wmma::row_major> Ah;
            wmma::load_matrix_sync(Ah, wh + (osub * 16) * QLDW + kk * 16, QLDW);
#pragma unroll
            for (int jn = 0; jn < 4; jn++) {
                wmma::fragment<wmma::matrix_b, 16, 16, 16, __half, wmma::row_major> Bh;
                wmma::load_matrix_sync(Bh, hh + (kk * 16) * QLDH + ph * 64 + jn * 16, QLDH);
                wmma::mma_sync(Cacc[jn], Ah, Bh, Cacc[jn]);
            }
        }
    }
    __syncthreads();
    float* Es = (float*)sm;
#pragma unroll
    for (int jn = 0; jn < 4; jn++)
        wmma::store_matrix_sync(Es + (osub * 16) * QLDE + ph * 64 + jn * 16, Cacc[jn], QLDE, wmma::mem_row_major);
    __syncthreads();
    for (int idx = tid; idx < 2048; idx += 256) {
        int o = idx >> 5, p4 = (idx & 31) << 2;
        float4 v = *(float4*)&Es[o * QLDE + p4];
        float bv = bias[o0 + o];
        size_t off = ((size_t)b * CC + o0 + o) * PP + p0 + p4;
        float4 xr = *(const float4*)(xin + off);
        v.x += bv + xr.x; v.y += bv + xr.y; v.z += bv + xr.z; v.w += bv + xr.w;
        *(float4*)(out + off) = v;
    }
}

// --------- attention: fp16 single-term, raw mma, 2 CTAs/SM ------------------
// smem: Q 0 (18432) | KV 18432 + (t&1)*18432 (K +0, V +9216) | Ls 55296
#define AKV0 18432
#define AKVB 18432
#define ALS  55296
#define ATTN_SMEM 55808

__device__ __forceinline__ void load_kv2(uint32_t base,
        const __half* k16, const __half* v16, int j0, int tid) {
    for (int idx = tid; idx < 1024; idx += 256) {
        int m = idx >> 9, r = (idx >> 3) & 63, c8 = idx & 7;
        uint32_t d = base + m * 9216 + r * 144 + c8 * 16;
        const __half* s = (m ? v16 : k16) + (size_t)(j0 + r) * 64 + c8 * 8;
        cpa16(d, s);
    }
}

__global__ __launch_bounds__(256, 2) void attn_mma() {
    extern __shared__ char sm[];
    uint32_t sb = smem_u32(sm);
    int tid = threadIdx.x, w = tid >> 5, lane = tid & 31;
    int bh = blockIdx.y, b = bh >> 3, nh = bh & 7;
    int i0 = blockIdx.x << 7;

    const __half* q16 = g_q16 + ((size_t)bh * PP + i0) * 64;
    const __half* k16 = g_k16 + (size_t)bh * PP * 64;
    const __half* v16 = g_v16 + (size_t)bh * PP * 64;

    for (int idx = tid; idx < 1024; idx += 256) {
        int r = idx >> 3, c8 = idx & 7;
        cpa16(sb + r * 144 + c8 * 16, q16 + (size_t)r * 64 + c8 * 8);
    }
    load_kv2(sb + AKV0, k16, v16, 0, tid);
    CPA_COMMIT();

    float O[8][4];
#pragma unroll
    for (int i = 0; i < 8; i++)
#pragma unroll
        for (int j = 0; j < 4; j++) O[i][j] = 0.f;
    float lsum0 = 0.f, lsum1 = 0.f;

    uint32_t lrow = (lane & 7) + ((lane >> 3) & 1) * 8;
    uint32_t lc16 = (uint32_t)(lane >> 4) * 16;
    uint32_t qrow = (uint32_t)(w * 16 + lrow) * 144 + lc16;

    for (int t = 0; t < 64; t++) {
        __syncthreads();
        if (t + 1 < 64) {
            load_kv2(sb + AKV0 + ((t + 1) & 1) * AKVB, k16, v16, (t + 1) * 64, tid);
            CPA_COMMIT(); CPA_WAIT1();
        } else CPA_WAIT0();
        __syncthreads();
        uint32_t kb = sb + AKV0 + (t & 1) * AKVB;

        // ---- S = QK^T ----
        float S[8][4];
#pragma unroll
        for (int i = 0; i < 8; i++)
#pragma unroll
            for (int j = 0; j < 4; j++) S[i][j] = 0.f;
#pragma unroll
        for (int s = 0; s < 4; s++) {
            uint32_t q4[4], k4[4];
            ldsm4(q4, sb + qrow + s * 32);
#pragma unroll
            for (int g = 0; g < 4; g++) {
                ldsm4(k4, kb + (uint32_t)(g * 16 + lrow) * 144 + s * 32 + lc16);
                mma16816h(S[2 * g], q4, k4[0], k4[2]);
                mma16816h(S[2 * g + 1], q4, k4[1], k4[3]);
            }
        }

        // ---- exp -> fp16 A-fragments (registers only) ----
        uint32_t Ph[4][4];
#pragma unroll
        for (int t8 = 0; t8 < 8; t8++) {
            float e0 = __expf(S[t8][0]), e1 = __expf(S[t8][1]);
            float e2 = __expf(S[t8][2]), e3 = __expf(S[t8][3]);
            lsum0 += e0 + e1; lsum1 += e2 + e3;
            int s = t8 >> 1, o = (t8 & 1) * 2;
            Ph[s][o] = cvt2h(e0, e1);
            Ph[s][o + 1] = cvt2h(e2, e3);
        }

        // ---- O += P V ----
#pragma unroll
        for (int s = 0; s < 4; s++) {
            uint32_t v4[4];
#pragma unroll
            for (int g = 0; g < 4; g++) {
                ldsm4t(v4, kb + 9216 + (uint32_t)(s * 16 + lrow) * 144 + g * 32 + lc16);
                mma16816h(O[2 * g], Ph[s], v4[0], v4[1]);
                mma16816h(O[2 * g + 1], Ph[s], v4[2], v4[3]);
            }
        }
    }

    float* Ls = (float*)(sm + ALS);
    lsum0 += __shfl_xor_sync(0xffffffffu, lsum0, 1);
    lsum0 += __shfl_xor_sync(0xffffffffu, lsum0, 2);
    lsum1 += __shfl_xor_sync(0xffffffffu, lsum1, 1);
    lsum1 += __shfl_xor_sync(0xffffffffu, lsum1, 2);
    int r0 = w * 16 + (lane >> 2);
    if ((lane & 3) == 0) { Ls[r0] = lsum0; Ls[r0 + 8] = lsum1; }
    __syncthreads();
    float inv0 = 1.f / Ls[r0], inv1 = 1.f / Ls[r0 + 8];
    float* Ss = (float*)sm;  // reuse Q + first KV buffer: 128 x 68 f32
    int cb = 2 * (lane & 3);
#pragma unroll
    for (int t8 = 0; t8 < 8; t8++) {
        int c = t8 * 8 + cb;
        Ss[r0 * 68 + c] = O[t8][0] * inv0;
        Ss[r0 * 68 + c + 1] = O[t8][1] * inv0;
        Ss[(r0 + 8) * 68 + c] = O[t8][2] * inv1;
        Ss[(r0 + 8) * 68 + c + 1] = O[t8][3] * inv1;
    }
    __syncthreads();
    __half* ah = g_at16 + ((size_t)b * CC + nh * 64) * PP + i0;
    for (int idx = tid; idx < 2048; idx += 256) {
        int d = idx >> 5, i4 = (idx & 31) << 2;
        uint2 hh;
        hh.x = cvt2h(Ss[(i4 + 0) * 68 + d], Ss[(i4 + 1) * 68 + d]);
        hh.y = cvt2h(Ss[(i4 + 2) * 68 + d], Ss[(i4 + 3) * 68 + d]);
        *(uint2*)(ah + (size_t)d * PP + i4) = hh;
    }
}

// ---------------------------------------------------------------------------
extern "C" void kernel_launch(void* const* d_in, const int* in_sizes, int n_in,
                              void* d_out, int out_size) {
    const float* x = (const float*)d_in[0];
    const float* qkv_w = (const float*)d_in[1];
    const float* proj_w = (const float*)d_in[2];
    const float* proj_b = (const float*)d_in[3];
    const float* gn_w = (const float*)d_in[4];
    const float* gn_b = (const float*)d_in[5];
    float* out = (float*)d_out;

    __half *wq16, *wp16;
    cudaGetSymbolAddress((void**)&wq16, g_wq16);
    cudaGetSymbolAddress((void**)&wp16, g_wp16);

    cudaFuncSetAttribute(qkv_wmma, cudaFuncAttributeMaxDynamicSharedMemorySize, QKV_SMEM);
    cudaFuncSetAttribute(proj_wmma, cudaFuncAttributeMaxDynamicSharedMemorySize, QKV_SMEM);
    cudaFuncSetAttribute(attn_mma, cudaFuncAttributeMaxDynamicSharedMemorySize, ATTN_SMEM);

    gn_kernel<<<BB * GG, 256>>>(x, gn_w, gn_b);
    wconv_kernel<<<512, 256>>>(qkv_w, wq16, 3 * CC * CC);
    wconv_kernel<<<256, 256>>>(proj_w, wp16, CC * CC);
    qkv_wmma<<<dim3(PP / 128, 24, BB), 256, QKV_SMEM>>>();
    attn_mma<<<dim3(PP / 128, NBH), 256, ATTN_SMEM>>>();
    proj_wmma<<<dim3(PP / 128, CC / 64, BB), 256, QKV_SMEM>>>(proj_b, x, out);
}

// round 12
// speedup vs baseline: 11.2666x; 1.0141x over previous
#include <cuda_runtime.h>
#include <cuda_fp16.h>
#include <mma.h>
#include <math.h>
#include <stdint.h>
using namespace nvcuda;

#define BB 2
#define CC 512
#define PP 4096
#define NBH 16
#define GG 32
#define CPG 16
#define EPSV 1e-5f

__device__ __align__(16) __half g_h16[BB * CC * PP];
__device__ __align__(16) __half g_wq16[3 * CC * CC];
__device__ __align__(16) __half g_wp16[CC * CC];
__device__ __align__(16) __half g_q16[NBH * PP * 64];
__device__ __align__(16) __half g_k16[NBH * PP * 64];
__device__ __align__(16) __half g_v16[NBH * PP * 64];
__device__ __align__(16) __half g_at16[BB * CC * PP];
__device__ float g_part[64 * 8 * 2];

__device__ __forceinline__ uint32_t smem_u32(const void* p) {
    uint32_t a;
    asm("{ .reg .u64 t; cvta.to.shared.u64 t, %1; cvt.u32.u64 %0, t; }" : "=r"(a) : "l"(p));
    return a;
}
__device__ __forceinline__ void cpa16(uint32_t dst, const void* src) {
    asm volatile("cp.async.cg.shared.global [%0], [%1], 16;" :: "r"(dst), "l"(src));
}
#define CPA_COMMIT() asm volatile("cp.async.commit_group;" ::: "memory")
#define CPA_WAIT1()  asm volatile("cp.async.wait_group 1;" ::: "memory")
#define CPA_WAIT0()  asm volatile("cp.async.wait_group 0;" ::: "memory")
__device__ __forceinline__ uint32_t cvt2h(float a, float b) {
    uint32_t r;
    asm("cvt.rn.f16x2.f32 %0, %1, %2;" : "=r"(r) : "f"(b), "f"(a));
    return r;
}
__device__ __forceinline__ void ldsm4(uint32_t* r, uint32_t a) {
    asm volatile("ldmatrix.sync.aligned.m8n8.x4.shared.b16 {%0,%1,%2,%3}, [%4];"
        : "=r"(r[0]), "=r"(r[1]), "=r"(r[2]), "=r"(r[3]) : "r"(a));
}
__device__ __forceinline__ void ldsm4t(uint32_t* r, uint32_t a) {
    asm volatile("ldmatrix.sync.aligned.m8n8.x4.trans.shared.b16 {%0,%1,%2,%3}, [%4];"
        : "=r"(r[0]), "=r"(r[1]), "=r"(r[2]), "=r"(r[3]) : "r"(a));
}
__device__ __forceinline__ void mma16816h(float* c, const uint32_t* a, uint32_t b0, uint32_t b1) {
    asm volatile("mma.sync.aligned.m16n8k16.row.col.f32.f16.f16.f32 "
        "{%0,%1,%2,%3}, {%4,%5,%6,%7}, {%8,%9}, {%0,%1,%2,%3};"
        : "+f"(c[0]), "+f"(c[1]), "+f"(c[2]), "+f"(c[3])
        : "r"(a[0]), "r"(a[1]), "r"(a[2]), "r"(a[3]), "r"(b0), "r"(b1));
}

// --------- GroupNorm phase 1: partial sums (full-chip) ----------------------
__global__ __launch_bounds__(256) void gn_stats(const float* __restrict__ x) {
    int bg = blockIdx.x, sl = blockIdx.y;
    int b = bg / GG, g = bg % GG;
    const float4* xp = (const float4*)(x + ((size_t)b * CC + g * CPG) * PP) + sl * 2048;
    float s = 0.f, s2 = 0.f;
    for (int i = threadIdx.x; i < 2048; i += 256) {
        float4 v = xp[i];
        s += v.x + v.y + v.z + v.w;
        s2 += v.x * v.x + v.y * v.y + v.z * v.z + v.w * v.w;
    }
    __shared__ float rs[256], rs2[256];
    rs[threadIdx.x] = s; rs2[threadIdx.x] = s2;
    __syncthreads();
    for (int o = 128; o > 0; o >>= 1) {
        if (threadIdx.x < o) { rs[threadIdx.x] += rs[threadIdx.x + o]; rs2[threadIdx.x] += rs2[threadIdx.x + o]; }
        __syncthreads();
    }
    if (threadIdx.x == 0) {
        g_part[(bg * 8 + sl) * 2] = rs[0];
        g_part[(bg * 8 + sl) * 2 + 1] = rs2[0];
    }
}

// --------- GroupNorm phase 2: apply -> fp16 (full-chip) ---------------------
__global__ __launch_bounds__(256) void gn_apply(const float* __restrict__ x,
        const float* __restrict__ gw, const float* __restrict__ gb) {
    int bg = blockIdx.x, sl = blockIdx.y;
    int b = bg / GG, g = bg % GG;
    float s = 0.f, s2 = 0.f;
#pragma unroll
    for (int i = 0; i < 8; i++) {
        s += g_part[(bg * 8 + i) * 2];
        s2 += g_part[(bg * 8 + i) * 2 + 1];
    }
    float mean = s / (float)(CPG * PP);
    float rstd = rsqrtf(s2 / (float)(CPG * PP) - mean * mean + EPSV);
    size_t base = ((size_t)b * CC + g * CPG) * PP;
    const float4* xp = (const float4*)(x + base);
    for (int ii = threadIdx.x; ii < 2048; ii += 256) {
        int i = sl * 2048 + ii;
        int c = g * CPG + (i >> 10);
        float ga = gw[c] * rstd, be = gb[c];
        float4 v = xp[i];
        uint2 hh;
        hh.x = cvt2h((v.x - mean) * ga + be, (v.y - mean) * ga + be);
        hh.y = cvt2h((v.z - mean) * ga + be, (v.w - mean) * ga + be);
        *(uint2*)(g_h16 + base + (size_t)i * 4) = hh;
    }
}

// --------- convert weights fp32 -> fp16 -------------------------------------
__global__ __launch_bounds__(256) void wconv_kernel(const float* __restrict__ w,
        __half* __restrict__ dh, int n) {
    for (int i = blockIdx.x * 256 + threadIdx.x; i < n; i += gridDim.x * 256) {
        dh[i] = __float2half_rn(w[i]);
    }
}

// --------- QKV GEMM (fp16 wmma) + fused transpose epilogue ------------------
#define QLDW 40
#define QLDH 136
#define QSTG 13824
#define QW_H 5120
#define QLDE 132
#define QKV_SMEM 34048

__global__ __launch_bounds__(256) void qkv_wmma() {
    extern __shared__ char sm[];
    uint32_t sb = smem_u32(sm);
    int tid = threadIdx.x, w = tid >> 5;
    int p0 = blockIdx.x << 7;
    int nh = blockIdx.y / 3, part = blockIdx.y % 3;
    int o0 = blockIdx.y << 6;
    int b = blockIdx.z, bh = b * 8 + nh;
    int osub = w >> 1, ph = w & 1;

    const __half* W = g_wq16 + (size_t)o0 * CC;
    const __half* H = g_h16 + (size_t)b * CC * PP;

    auto stage = [&](int buf, int k0) {
        uint32_t bs = sb + buf * QSTG;
        for (int idx = tid; idx < 256; idx += 256) {
            int r = idx >> 2, c8 = idx & 3;
            cpa16(bs + r * 80 + c8 * 16, W + (size_t)r * CC + k0 + c8 * 8);
        }
        for (int idx = tid; idx < 512; idx += 256) {
            int r = idx >> 4, c8 = idx & 15;
            cpa16(bs + QW_H + r * 272 + c8 * 16, H + (size_t)(k0 + r) * PP + p0 + c8 * 8);
        }
    };

    wmma::fragment<wmma::accumulator, 16, 16, 16, float> Cacc[4];
#pragma unroll
    for (int i = 0; i < 4; i++) wmma::fill_fragment(Cacc[i], 0.f);

    stage(0, 0);
    CPA_COMMIT();
    for (int kc = 0; kc < 16; kc++) {
        __syncthreads();
        if (kc + 1 < 16) { stage((kc + 1) & 1, (kc + 1) * 32); CPA_COMMIT(); CPA_WAIT1(); }
        else CPA_WAIT0();
        __syncthreads();
        const char* bs = sm + (kc & 1) * QSTG;
        const __half* wh = (const __half*)bs;
        const __half* hh = (const __half*)(bs + QW_H);
#pragma unroll
        for (int kk = 0; kk < 2; kk++) {
            wmma::fragment<wmma::matrix_a, 16, 16, 16, __half, wmma::row_major> Ah;
            wmma::load_matrix_sync(Ah, wh + (osub * 16) * QLDW + kk * 16, QLDW);
#pragma unroll
            for (int jn = 0; jn < 4; jn++) {
                wmma::fragment<wmma::matrix_b, 16, 16, 16, __half, wmma::row_major> Bh;
                wmma::load_matrix_sync(Bh, hh + (kk * 16) * QLDH + ph * 64 + jn * 16, QLDH);
                wmma::mma_sync(Cacc[jn], Ah, Bh, Cacc[jn]);
            }
        }
    }
    __syncthreads();
    float* Es = (float*)sm;
#pragma unroll
    for (int jn = 0; jn < 4; jn++)
        wmma::store_matrix_sync(Es + (osub * 16) * QLDE + ph * 64 + jn * 16, Cacc[jn], QLDE, wmma::mem_row_major);
    __syncthreads();
    __half* dh = (part == 0 ? g_q16 : part == 1 ? g_k16 : g_v16) + (size_t)bh * PP * 64;
    float scale = (part == 0) ? 0.125f : 1.0f;
    for (int idx = tid; idx < 2048; idx += 256) {
        int p = idx >> 4, d4 = (idx & 15) << 2;
        uint2 hh;
        hh.x = cvt2h(Es[(d4 + 0) * QLDE + p] * scale, Es[(d4 + 1) * QLDE + p] * scale);
        hh.y = cvt2h(Es[(d4 + 2) * QLDE + p] * scale, Es[(d4 + 3) * QLDE + p] * scale);
        *(uint2*)(dh + (size_t)(p0 + p) * 64 + d4) = hh;
    }
}

// --------- proj GEMM (fp16 wmma) + bias + residual --------------------------
__global__ __launch_bounds__(256) void proj_wmma(const float* __restrict__ bias,
        const float* __restrict__ xin, float* __restrict__ out) {
    extern __shared__ char sm[];
    uint32_t sb = smem_u32(sm);
    int tid = threadIdx.x, w = tid >> 5;
    int p0 = blockIdx.x << 7;
    int o0 = blockIdx.y << 6;
    int b = blockIdx.z;
    int osub = w >> 1, ph = w & 1;

    const __half* W = g_wp16 + (size_t)o0 * CC;
    const __half* H = g_at16 + (size_t)b * CC * PP;

    auto stage = [&](int buf, int k0) {
        uint32_t bs = sb + buf * QSTG;
        for (int idx = tid; idx < 256; idx += 256) {
            int r = idx >> 2, c8 = idx & 3;
            cpa16(bs + r * 80 + c8 * 16, W + (size_t)r * CC + k0 + c8 * 8);
        }
        for (int idx = tid; idx < 512; idx += 256) {
            int r = idx >> 4, c8 = idx & 15;
            cpa16(bs + QW_H + r * 272 + c8 * 16, H + (size_t)(k0 + r) * PP + p0 + c8 * 8);
        }
    };

    wmma::fragment<wmma::accumulator, 16, 16, 16, float> Cacc[4];
#pragma unroll
    for (int i = 0; i < 4; i++) wmma::fill_fragment(Cacc[i], 0.f);

    stage(0, 0);
    CPA_COMMIT();
    for (int kc = 0; kc < 16; kc++) {
        __syncthreads();
        if (kc + 1 < 16) { stage((kc + 1) & 1, (kc + 1) * 32); CPA_COMMIT(); CPA_WAIT1(); }
        else CPA_WAIT0();
        __syncthreads();
        const char* bs = sm + (kc & 1) * QSTG;
        const __half* wh = (const __half*)bs;
        const __half* hh = (const __half*)(bs + QW_H);
#pragma unroll
        for (int kk = 0; kk < 2; kk++) {
            wmma::fragment<wmma::matrix_a, 16, 16, 16, __half, wmma::row_major> Ah;
            wmma::load_matrix_sync(Ah, wh + (osub * 16) * QLDW + kk * 16, QLDW);
#pragma unroll
            for (int jn = 0; jn < 4; jn++) {
                wmma::fragment<wmma::matrix_b, 16, 16, 16, __half, wmma::row_major> Bh;
                wmma::load_matrix_sync(Bh, hh + (kk * 16) * QLDH + ph * 64 + jn * 16, QLDH);
                wmma::mma_sync(Cacc[jn], Ah, Bh, Cacc[jn]);
            }
        }
    }
    __syncthreads();
    float* Es = (float*)sm;
#pragma unroll
    for (int jn = 0; jn < 4; jn++)
        wmma::store_matrix_sync(Es + (osub * 16) * QLDE + ph * 64 + jn * 16, Cacc[jn], QLDE, wmma::mem_row_major);
    __syncthreads();
    for (int idx = tid; idx < 2048; idx += 256) {
        int o = idx >> 5, p4 = (idx & 31) << 2;
        float4 v = *(float4*)&Es[o * QLDE + p4];
        float bv = bias[o0 + o];
        size_t off = ((size_t)b * CC + o0 + o) * PP + p0 + p4;
        float4 xr = *(const float4*)(xin + off);
        v.x += bv + xr.x; v.y += bv + xr.y; v.z += bv + xr.z; v.w += bv + xr.w;
        *(float4*)(out + off) = v;
    }
}

// --------- attention: reg-resident Q frags, 128-key staging -----------------
// smem: KV double buffer 0/36864 (K +0 128x144, V +18432 128x144) | Ls 73728
#define AKVB 36864
#define ALS  73728
#define ATTN_SMEM 74240

__device__ __forceinline__ void load_kv2(uint32_t base,
        const __half* k16, const __half* v16, int j0, int tid) {
    for (int idx = tid; idx < 2048; idx += 256) {
        int m = idx >> 10, r = (idx >> 3) & 127, c8 = idx & 7;
        uint32_t d = base + m * 18432 + r * 144 + c8 * 16;
        const __half* s = (m ? v16 : k16) + (size_t)(j0 + r) * 64 + c8 * 8;
        cpa16(d, s);
    }
}

__global__ __launch_bounds__(256, 2) void attn_mma() {
    extern __shared__ char sm[];
    uint32_t sb = smem_u32(sm);
    int tid = threadIdx.x, w = tid >> 5, lane = tid & 31;
    int bh = blockIdx.y, b = bh >> 3, nh = bh & 7;
    int i0 = blockIdx.x << 7;

    const __half* q16 = g_q16 + ((size_t)bh * PP + i0) * 64;
    const __half* k16 = g_k16 + (size_t)bh * PP * 64;
    const __half* v16 = g_v16 + (size_t)bh * PP * 64;

    uint32_t lrow = (lane & 7) + ((lane >> 3) & 1) * 8;
    uint32_t lc16 = (uint32_t)(lane >> 4) * 16;
    uint32_t qrow = (uint32_t)(w * 16 + lrow) * 144 + lc16;

    // stage Q into buffer0 area, hoist fragments to registers
    for (int idx = tid; idx < 1024; idx += 256) {
        int r = idx >> 3, c8 = idx & 7;
        cpa16(sb + r * 144 + c8 * 16, q16 + (size_t)r * 64 + c8 * 8);
    }
    CPA_COMMIT(); CPA_WAIT0();
    __syncthreads();
    uint32_t Qf[4][4];
#pragma unroll
    for (int s = 0; s < 4; s++) ldsm4(Qf[s], sb + qrow + s * 32);
    __syncthreads();

    load_kv2(sb, k16, v16, 0, tid);
    CPA_COMMIT();

    float O[8][4];
#pragma unroll
    for (int i = 0; i < 8; i++)
#pragma unroll
        for (int j = 0; j < 4; j++) O[i][j] = 0.f;
    float lsum0 = 0.f, lsum1 = 0.f;

    for (int t = 0; t < 32; t++) {
        __syncthreads();
        if (t + 1 < 32) {
            load_kv2(sb + ((t + 1) & 1) * AKVB, k16, v16, (t + 1) * 128, tid);
            CPA_COMMIT(); CPA_WAIT1();
        } else CPA_WAIT0();
        __syncthreads();
        uint32_t kb = sb + (t & 1) * AKVB;

#pragma unroll
        for (int half = 0; half < 2; half++) {
            uint32_t jb = (uint32_t)half * 64 * 144;
            // ---- S = QK^T ----
            float S[8][4];
#pragma unroll
            for (int i = 0; i < 8; i++)
#pragma unroll
                for (int j = 0; j < 4; j++) S[i][j] = 0.f;
#pragma unroll
            for (int s = 0; s < 4; s++) {
                uint32_t k4[4];
#pragma unroll
                for (int g = 0; g < 4; g++) {
                    ldsm4(k4, kb + jb + (uint32_t)(g * 16 + lrow) * 144 + s * 32 + lc16);
                    mma16816h(S[2 * g], Qf[s], k4[0], k4[2]);
                    mma16816h(S[2 * g + 1], Qf[s], k4[1], k4[3]);
                }
            }
            // ---- exp -> fp16 A-fragments ----
            uint32_t Ph[4][4];
#pragma unroll
            for (int t8 = 0; t8 < 8; t8++) {
                float e0 = __expf(S[t8][0]), e1 = __expf(S[t8][1]);
                float e2 = __expf(S[t8][2]), e3 = __expf(S[t8][3]);
                lsum0 += e0 + e1; lsum1 += e2 + e3;
                int s = t8 >> 1, o = (t8 & 1) * 2;
                Ph[s][o] = cvt2h(e0, e1);
                Ph[s][o + 1] = cvt2h(e2, e3);
            }
            // ---- O += P V ----
#pragma unroll
            for (int s = 0; s < 4; s++) {
                uint32_t v4[4];
#pragma unroll
                for (int g = 0; g < 4; g++) {
                    ldsm4t(v4, kb + 18432 + jb + (uint32_t)(s * 16 + lrow) * 144 + g * 32 + lc16);
                    mma16816h(O[2 * g], Ph[s], v4[0], v4[1]);
                    mma16816h(O[2 * g + 1], Ph[s], v4[2], v4[3]);
                }
            }
        }
    }

    float* Ls = (float*)(sm + ALS);
    lsum0 += __shfl_xor_sync(0xffffffffu, lsum0, 1);
    lsum0 += __shfl_xor_sync(0xffffffffu, lsum0, 2);
    lsum1 += __shfl_xor_sync(0xffffffffu, lsum1, 1);
    lsum1 += __shfl_xor_sync(0xffffffffu, lsum1, 2);
    int r0 = w * 16 + (lane >> 2);
    if ((lane & 3) == 0) { Ls[r0] = lsum0; Ls[r0 + 8] = lsum1; }
    __syncthreads();
    float inv0 = 1.f / Ls[r0], inv1 = 1.f / Ls[r0 + 8];
    float* Ss = (float*)sm;  // 128 x 68 f32 = 34816 <= 36864 (buffer0 area)
    int cb = 2 * (lane & 3);
#pragma unroll
    for (int t8 = 0; t8 < 8; t8++) {
        int c = t8 * 8 + cb;
        Ss[r0 * 68 + c] = O[t8][0] * inv0;
        Ss[r0 * 68 + c + 1] = O[t8][1] * inv0;
        Ss[(r0 + 8) * 68 + c] = O[t8][2] * inv1;
        Ss[(r0 + 8) * 68 + c + 1] = O[t8][3] * inv1;
    }
    __syncthreads();
    __half* ah = g_at16 + ((size_t)b * CC + nh * 64) * PP + i0;
    for (int idx = tid; idx < 2048; idx += 256) {
        int d = idx >> 5, i4 = (idx & 31) << 2;
        uint2 hh;
        hh.x = cvt2h(Ss[(i4 + 0) * 68 + d], Ss[(i4 + 1) * 68 + d]);
        hh.y = cvt2h(Ss[(i4 + 2) * 68 + d], Ss[(i4 + 3) * 68 + d]);
        *(uint2*)(ah + (size_t)d * PP + i4) = hh;
    }
}

// ---------------------------------------------------------------------------
extern "C" void kernel_launch(void* const* d_in, const int* in_sizes, int n_in,
                              void* d_out, int out_size) {
    const float* x = (const float*)d_in[0];
    const float* qkv_w = (const float*)d_in[1];
    const float* proj_w = (const float*)d_in[2];
    const float* proj_b = (const float*)d_in[3];
    const float* gn_w = (const float*)d_in[4];
    const float* gn_b = (const float*)d_in[5];
    float* out = (float*)d_out;

    __half *wq16, *wp16;
    cudaGetSymbolAddress((void**)&wq16, g_wq16);
    cudaGetSymbolAddress((void**)&wp16, g_wp16);

    cudaFuncSetAttribute(qkv_wmma, cudaFuncAttributeMaxDynamicSharedMemorySize, QKV_SMEM);
    cudaFuncSetAttribute(proj_wmma, cudaFuncAttributeMaxDynamicSharedMemorySize, QKV_SMEM);
    cudaFuncSetAttribute(attn_mma, cudaFuncAttributeMaxDynamicSharedMemorySize, ATTN_SMEM);

    gn_stats<<<dim3(BB * GG, 8), 256>>>(x);
    wconv_kernel<<<512, 256>>>(qkv_w, wq16, 3 * CC * CC);
    wconv_kernel<<<256, 256>>>(proj_w, wp16, CC * CC);
    gn_apply<<<dim3(BB * GG, 8), 256>>>(x, gn_w, gn_b);
    qkv_wmma<<<dim3(PP / 128, 24, BB), 256, QKV_SMEM>>>();
    attn_mma<<<dim3(PP / 128, NBH), 256, ATTN_SMEM>>>();
    proj_wmma<<<dim3(PP / 128, CC / 64, BB), 256, QKV_SMEM>>>(proj_b, x, out);
}

// round 13
// speedup vs baseline: 11.6937x; 1.0379x over previous
#include <cuda_runtime.h>
#include <cuda_fp16.h>
#include <math.h>
#include <stdint.h>

#define BB 2
#define CC 512
#define PP 4096
#define NBH 16
#define GG 32
#define CPG 16
#define EPSV 1e-5f

__device__ __align__(16) __half g_h16[BB * CC * PP];
__device__ __align__(16) __half g_wq16[3 * CC * CC];
__device__ __align__(16) __half g_wp16[CC * CC];
__device__ __align__(16) __half g_q16[NBH * PP * 64];
__device__ __align__(16) __half g_k16[NBH * PP * 64];
__device__ __align__(16) __half g_v16[NBH * PP * 64];
__device__ __align__(16) __half g_at16[BB * CC * PP];
__device__ float g_part[64 * 8 * 2];

__device__ __forceinline__ uint32_t smem_u32(const void* p) {
    uint32_t a;
    asm("{ .reg .u64 t; cvta.to.shared.u64 t, %1; cvt.u32.u64 %0, t; }" : "=r"(a) : "l"(p));
    return a;
}
__device__ __forceinline__ void cpa16(uint32_t dst, const void* src) {
    asm volatile("cp.async.cg.shared.global [%0], [%1], 16;" :: "r"(dst), "l"(src));
}
#define CPA_COMMIT() asm volatile("cp.async.commit_group;" ::: "memory")
#define CPA_WAIT1()  asm volatile("cp.async.wait_group 1;" ::: "memory")
#define CPA_WAIT0()  asm volatile("cp.async.wait_group 0;" ::: "memory")
__device__ __forceinline__ uint32_t cvt2h(float a, float b) {
    uint32_t r;
    asm("cvt.rn.f16x2.f32 %0, %1, %2;" : "=r"(r) : "f"(b), "f"(a));
    return r;
}
__device__ __forceinline__ void ldsm4(uint32_t* r, uint32_t a) {
    asm volatile("ldmatrix.sync.aligned.m8n8.x4.shared.b16 {%0,%1,%2,%3}, [%4];"
        : "=r"(r[0]), "=r"(r[1]), "=r"(r[2]), "=r"(r[3]) : "r"(a));
}
__device__ __forceinline__ void ldsm4t(uint32_t* r, uint32_t a) {
    asm volatile("ldmatrix.sync.aligned.m8n8.x4.trans.shared.b16 {%0,%1,%2,%3}, [%4];"
        : "=r"(r[0]), "=r"(r[1]), "=r"(r[2]), "=r"(r[3]) : "r"(a));
}
__device__ __forceinline__ void mma16816h(float* c, const uint32_t* a, uint32_t b0, uint32_t b1) {
    asm volatile("mma.sync.aligned.m16n8k16.row.col.f32.f16.f16.f32 "
        "{%0,%1,%2,%3}, {%4,%5,%6,%7}, {%8,%9}, {%0,%1,%2,%3};"
        : "+f"(c[0]), "+f"(c[1]), "+f"(c[2]), "+f"(c[3])
        : "r"(a[0]), "r"(a[1]), "r"(a[2]), "r"(a[3]), "r"(b0), "r"(b1));
}

#define LOG2E 1.44269504088896f

// --------- GroupNorm phase 1: partial sums (full-chip) ----------------------
__global__ __launch_bounds__(256) void gn_stats(const float* __restrict__ x) {
    int bg = blockIdx.x, sl = blockIdx.y;
    int b = bg / GG, g = bg % GG;
    const float4* xp = (const float4*)(x + ((size_t)b * CC + g * CPG) * PP) + sl * 2048;
    float s = 0.f, s2 = 0.f;
    for (int i = threadIdx.x; i < 2048; i += 256) {
        float4 v = xp[i];
        s += v.x + v.y + v.z + v.w;
        s2 += v.x * v.x + v.y * v.y + v.z * v.z + v.w * v.w;
    }
    __shared__ float rs[256], rs2[256];
    rs[threadIdx.x] = s; rs2[threadIdx.x] = s2;
    __syncthreads();
    for (int o = 128; o > 0; o >>= 1) {
        if (threadIdx.x < o) { rs[threadIdx.x] += rs[threadIdx.x + o]; rs2[threadIdx.x] += rs2[threadIdx.x + o]; }
        __syncthreads();
    }
    if (threadIdx.x == 0) {
        g_part[(bg * 8 + sl) * 2] = rs[0];
        g_part[(bg * 8 + sl) * 2 + 1] = rs2[0];
    }
}

// --------- GroupNorm phase 2: apply -> fp16 ---------------------------------
__global__ __launch_bounds__(256) void gn_apply(const float* __restrict__ x,
        const float* __restrict__ gw, const float* __restrict__ gb) {
    int bg = blockIdx.x, sl = blockIdx.y;
    int b = bg / GG, g = bg % GG;
    float s = 0.f, s2 = 0.f;
#pragma unroll
    for (int i = 0; i < 8; i++) {
        s += g_part[(bg * 8 + i) * 2];
        s2 += g_part[(bg * 8 + i) * 2 + 1];
    }
    float mean = s / (float)(CPG * PP);
    float rstd = rsqrtf(s2 / (float)(CPG * PP) - mean * mean + EPSV);
    size_t base = ((size_t)b * CC + g * CPG) * PP;
    const float4* xp = (const float4*)(x + base);
    for (int ii = threadIdx.x; ii < 2048; ii += 256) {
        int i = sl * 2048 + ii;
        int c = g * CPG + (i >> 10);
        float ga = gw[c] * rstd, be = gb[c];
        float4 v = xp[i];
        uint2 hh;
        hh.x = cvt2h((v.x - mean) * ga + be, (v.y - mean) * ga + be);
        hh.y = cvt2h((v.z - mean) * ga + be, (v.w - mean) * ga + be);
        *(uint2*)(g_h16 + base + (size_t)i * 4) = hh;
    }
}

// --------- convert weights fp32 -> fp16 -------------------------------------
__global__ __launch_bounds__(256) void wconv_kernel(const float* __restrict__ w,
        __half* __restrict__ dh, int n) {
    for (int i = blockIdx.x * 256 + threadIdx.x; i < n; i += gridDim.x * 256) {
        dh[i] = __float2half_rn(w[i]);
    }
}

// --------- raw-mma GEMM core: 8 warps (2 o x 4 p), CTA 64o x 256p -----------
// stage: W 64x(32B data in 48B slot) = 3072 | H 16x(512B in 528B) = 8448
#define XSTG 11520
#define XW_H 3072
#define X_SMEM 36864   // epilogue (qkv) 256 x 144B dominates

// C[2][8][4] accumulators; returns after k-loop with C filled
__device__ __forceinline__ void gemm_core(uint32_t sb, const __half* W, const __half* H,
        size_t hstride_b, int p0, int tid, float C[2][8][4], int lane, int wo, int wp) {
    auto stage = [&](int buf, int k0) {
        uint32_t bs = sb + buf * XSTG;
        for (int idx = tid; idx < 128; idx += 256) {
            int r = idx >> 1, c = idx & 1;
            cpa16(bs + r * 48 + c * 16, W + (size_t)r * CC + k0 + c * 8);
        }
        for (int idx = tid; idx < 512; idx += 256) {
            int r = idx >> 5, c = idx & 31;
            cpa16(bs + XW_H + r * 528 + c * 16, H + (size_t)(k0 + r) * PP + p0 + c * 8);
        }
    };
    uint32_t lrow = (lane & 7) + ((lane >> 3) & 1) * 8;
    uint32_t lc16 = (uint32_t)(lane >> 4) * 16;

    stage(0, 0);
    CPA_COMMIT();
    for (int kc = 0; kc < 32; kc++) {
        __syncthreads();
        if (kc + 1 < 32) { stage((kc + 1) & 1, (kc + 1) * 16); CPA_COMMIT(); CPA_WAIT1(); }
        else CPA_WAIT0();
        __syncthreads();
        uint32_t bs = sb + (kc & 1) * XSTG;
        uint32_t A[2][4];
#pragma unroll
        for (int mt = 0; mt < 2; mt++)
            ldsm4(A[mt], bs + (uint32_t)(wo * 32 + mt * 16 + lrow) * 48 + lc16);
#pragma unroll
        for (int pt = 0; pt < 4; pt++) {
            uint32_t B4[4];
            ldsm4t(B4, bs + XW_H + lrow * 528 + (uint32_t)wp * 128 + pt * 32 + lc16);
#pragma unroll
            for (int mt = 0; mt < 2; mt++) {
                mma16816h(C[mt][2 * pt], A[mt], B4[0], B4[1]);
                mma16816h(C[mt][2 * pt + 1], A[mt], B4[2], B4[3]);
            }
        }
    }
}

// --------- QKV GEMM + fused transpose epilogue (token-major fp16) -----------
__global__ __launch_bounds__(256) void qkv_mma() {
    extern __shared__ char sm[];
    uint32_t sb = smem_u32(sm);
    int tid = threadIdx.x, w = tid >> 5, lane = tid & 31;
    int p0 = blockIdx.x << 8;
    int nh = blockIdx.y / 3, part = blockIdx.y % 3;
    int o0 = blockIdx.y << 6;
    int b = blockIdx.z, bh = b * 8 + nh;
    int wo = w >> 2, wp = w & 3;

    float C[2][8][4];
#pragma unroll
    for (int i = 0; i < 2; i++)
#pragma unroll
        for (int j = 0; j < 8; j++)
#pragma unroll
            for (int k = 0; k < 4; k++) C[i][j][k] = 0.f;

    gemm_core(sb, g_wq16 + (size_t)o0 * CC, g_h16 + (size_t)b * CC * PP,
              0, p0, tid, C, lane, wo, wp);

    // epilogue: scale, cvt fp16, store transposed [p][64 d] via smem
    float scale = (part == 0) ? 0.125f * LOG2E : 1.0f;
    __syncthreads();
    __half* Sp = (__half*)sm;  // [256 p][72 halfs]
    int r = lane >> 2, cb = 2 * (lane & 3);
#pragma unroll
    for (int mt = 0; mt < 2; mt++) {
        int ol = wo * 32 + mt * 16 + r;
#pragma unroll
        for (int n8 = 0; n8 < 8; n8++) {
            int p = wp * 64 + n8 * 8 + cb;
            Sp[(p + 0) * 72 + ol] = __float2half_rn(C[mt][n8][0] * scale);
            Sp[(p + 1) * 72 + ol] = __float2half_rn(C[mt][n8][1] * scale);
            Sp[(p + 0) * 72 + ol + 8] = __float2half_rn(C[mt][n8][2] * scale);
            Sp[(p + 1) * 72 + ol + 8] = __float2half_rn(C[mt][n8][3] * scale);
        }
    }
    __syncthreads();
    __half* dh = (part == 0 ? g_q16 : part == 1 ? g_k16 : g_v16) + (size_t)bh * PP * 64;
    for (int idx = tid; idx < 2048; idx += 256) {
        int p = idx >> 3, c = idx & 7;
        *(uint4*)(dh + (size_t)(p0 + p) * 64 + c * 8) = *(uint4*)((char*)sm + p * 144 + c * 16);
    }
}

// --------- proj GEMM + bias + residual (direct fp32 epilogue) ---------------
__global__ __launch_bounds__(256) void proj_mma(const float* __restrict__ bias,
        const float* __restrict__ xin, float* __restrict__ out) {
    extern __shared__ char sm[];
    uint32_t sb = smem_u32(sm);
    int tid = threadIdx.x, w = tid >> 5, lane = tid & 31;
    int p0 = blockIdx.x << 8;
    int o0 = blockIdx.y << 6;
    int b = blockIdx.z;
    int wo = w >> 2, wp = w & 3;

    float C[2][8][4];
#pragma unroll
    for (int i = 0; i < 2; i++)
#pragma unroll
        for (int j = 0; j < 8; j++)
#pragma unroll
            for (int k = 0; k < 4; k++) C[i][j][k] = 0.f;

    gemm_core(sb, g_wp16 + (size_t)o0 * CC, g_at16 + (size_t)b * CC * PP,
              0, p0, tid, C, lane, wo, wp);

    int r = lane >> 2, cb = 2 * (lane & 3);
#pragma unroll
    for (int mt = 0; mt < 2; mt++) {
        int o = o0 + wo * 32 + mt * 16 + r;
        float bv0 = bias[o], bv1 = bias[o + 8];
#pragma unroll
        for (int n8 = 0; n8 < 8; n8++) {
            int p = p0 + wp * 64 + n8 * 8 + cb;
            size_t off0 = ((size_t)b * CC + o) * PP + p;
            size_t off1 = ((size_t)b * CC + o + 8) * PP + p;
            float2 r0 = *(const float2*)(xin + off0);
            float2 r1 = *(const float2*)(xin + off1);
            float2 v0 = make_float2(C[mt][n8][0] + bv0 + r0.x, C[mt][n8][1] + bv0 + r0.y);
            float2 v1 = make_float2(C[mt][n8][2] + bv1 + r1.x, C[mt][n8][3] + bv1 + r1.y);
            *(float2*)(out + off0) = v0;
            *(float2*)(out + off1) = v1;
        }
    }
}

// --------- attention: fp16x2 exp, reg-resident Q, 128-key staging -----------
#define AKVB 36864
#define ALS  73728
#define ATTN_SMEM 74240

__device__ __forceinline__ void load_kv2(uint32_t base,
        const __half* k16, const __half* v16, int j0, int tid) {
    for (int idx = tid; idx < 2048; idx += 256) {
        int m = idx >> 10, r = (idx >> 3) & 127, c8 = idx & 7;
        uint32_t d = base + m * 18432 + r * 144 + c8 * 16;
        const __half* s = (m ? v16 : k16) + (size_t)(j0 + r) * 64 + c8 * 8;
        cpa16(d, s);
    }
}

__global__ __launch_bounds__(256, 2) void attn_mma() {
    extern __shared__ char sm[];
    uint32_t sb = smem_u32(sm);
    int tid = threadIdx.x, w = tid >> 5, lane = tid & 31;
    int bh = blockIdx.y, b = bh >> 3, nh = bh & 7;
    int i0 = blockIdx.x << 7;

    const __half* q16 = g_q16 + ((size_t)bh * PP + i0) * 64;
    const __half* k16 = g_k16 + (size_t)bh * PP * 64;
    const __half* v16 = g_v16 + (size_t)bh * PP * 64;

    uint32_t lrow = (lane & 7) + ((lane >> 3) & 1) * 8;
    uint32_t lc16 = (uint32_t)(lane >> 4) * 16;
    uint32_t qrow = (uint32_t)(w * 16 + lrow) * 144 + lc16;

    for (int idx = tid; idx < 1024; idx += 256) {
        int r = idx >> 3, c8 = idx & 7;
        cpa16(sb + r * 144 + c8 * 16, q16 + (size_t)r * 64 + c8 * 8);
    }
    CPA_COMMIT(); CPA_WAIT0();
    __syncthreads();
    uint32_t Qf[4][4];
#pragma unroll
    for (int s = 0; s < 4; s++) ldsm4(Qf[s], sb + qrow + s * 32);
    __syncthreads();

    load_kv2(sb, k16, v16, 0, tid);
    CPA_COMMIT();

    float O[8][4];
#pragma unroll
    for (int i = 0; i < 8; i++)
#pragma unroll
        for (int j = 0; j < 4; j++) O[i][j] = 0.f;
    float lsum0 = 0.f, lsum1 = 0.f;

    for (int t = 0; t < 32; t++) {
        __syncthreads();
        if (t + 1 < 32) {
            load_kv2(sb + ((t + 1) & 1) * AKVB, k16, v16, (t + 1) * 128, tid);
            CPA_COMMIT(); CPA_WAIT1();
        } else CPA_WAIT0();
        __syncthreads();
        uint32_t kb = sb + (t & 1) * AKVB;

#pragma unroll
        for (int half = 0; half < 2; half++) {
            uint32_t jb = (uint32_t)half * 64 * 144;
            float S[8][4];
#pragma unroll
            for (int i = 0; i < 8; i++)
#pragma unroll
                for (int j = 0; j < 4; j++) S[i][j] = 0.f;
#pragma unroll
            for (int s = 0; s < 4; s++) {
                uint32_t k4[4];
#pragma unroll
                for (int g = 0; g < 4; g++) {
                    ldsm4(k4, kb + jb + (uint32_t)(g * 16 + lrow) * 144 + s * 32 + lc16);
                    mma16816h(S[2 * g], Qf[s], k4[0], k4[2]);
                    mma16816h(S[2 * g + 1], Qf[s], k4[1], k4[3]);
                }
            }
            // ---- exp2 in f16x2 (S already scaled by log2e upstream) ----
            uint32_t Ph[4][4];
            __half2 sum0 = __float2half2_rn(0.f), sum1 = __float2half2_rn(0.f);
#pragma unroll
            for (int t8 = 0; t8 < 8; t8++) {
                __half2 x01 = __floats2half2_rn(S[t8][0], S[t8][1]);
                __half2 x23 = __floats2half2_rn(S[t8][2], S[t8][3]);
                __half2 e01 = h2exp2(x01);
                __half2 e23 = h2exp2(x23);
                int s = t8 >> 1, o = (t8 & 1) * 2;
                Ph[s][o] = *(uint32_t*)&e01;
                Ph[s][o + 1] = *(uint32_t*)&e23;
                sum0 = __hadd2(sum0, e01);
                sum1 = __hadd2(sum1, e23);
            }
            lsum0 += __low2float(sum0) + __high2float(sum0);
            lsum1 += __low2float(sum1) + __high2float(sum1);
            // ---- O += P V ----
#pragma unroll
            for (int s = 0; s < 4; s++) {
                uint32_t v4[4];
#pragma unroll
                for (int g = 0; g < 4; g++) {
                    ldsm4t(v4, kb + 18432 + jb + (uint32_t)(s * 16 + lrow) * 144 + g * 32 + lc16);
                    mma16816h(O[2 * g], Ph[s], v4[0], v4[1]);
                    mma16816h(O[2 * g + 1], Ph[s], v4[2], v4[3]);
                }
            }
        }
    }

    float* Ls = (float*)(sm + ALS);
    lsum0 += __shfl_xor_sync(0xffffffffu, lsum0, 1);
    lsum0 += __shfl_xor_sync(0xffffffffu, lsum0, 2);
    lsum1 += __shfl_xor_sync(0xffffffffu, lsum1, 1);
    lsum1 += __shfl_xor_sync(0xffffffffu, lsum1, 2);
    int r0 = w * 16 + (lane >> 2);
    if ((lane & 3) == 0) { Ls[r0] = lsum0; Ls[r0 + 8] = lsum1; }
    __syncthreads();
    float inv0 = 1.f / Ls[r0], inv1 = 1.f / Ls[r0 + 8];
    float* Ss = (float*)sm;
    int cb = 2 * (lane & 3);
#pragma unroll
    for (int t8 = 0; t8 < 8; t8++) {
        int c = t8 * 8 + cb;
        Ss[r0 * 68 + c] = O[t8][0] * inv0;
        Ss[r0 * 68 + c + 1] = O[t8][1] * inv0;
        Ss[(r0 + 8) * 68 + c] = O[t8][2] * inv1;
        Ss[(r0 + 8) * 68 + c + 1] = O[t8][3] * inv1;
    }
    __syncthreads();
    __half* ah = g_at16 + ((size_t)b * CC + nh * 64) * PP + i0;
    for (int idx = tid; idx < 2048; idx += 256) {
        int d = idx >> 5, i4 = (idx & 31) << 2;
        uint2 hh;
        hh.x = cvt2h(Ss[(i4 + 0) * 68 + d], Ss[(i4 + 1) * 68 + d]);
        hh.y = cvt2h(Ss[(i4 + 2) * 68 + d], Ss[(i4 + 3) * 68 + d]);
        *(uint2*)(ah + (size_t)d * PP + i4) = hh;
    }
}

// ---------------------------------------------------------------------------
extern "C" void kernel_launch(void* const* d_in, const int* in_sizes, int n_in,
                              void* d_out, int out_size) {
    const float* x = (const float*)d_in[0];
    const float* qkv_w = (const float*)d_in[1];
    const float* proj_w = (const float*)d_in[2];
    const float* proj_b = (const float*)d_in[3];
    const float* gn_w = (const float*)d_in[4];
    const float* gn_b = (const float*)d_in[5];
    float* out = (float*)d_out;

    __half *wq16, *wp16;
    cudaGetSymbolAddress((void**)&wq16, g_wq16);
    cudaGetSymbolAddress((void**)&wp16, g_wp16);

    cudaFuncSetAttribute(qkv_mma, cudaFuncAttributeMaxDynamicSharedMemorySize, X_SMEM);
    cudaFuncSetAttribute(proj_mma, cudaFuncAttributeMaxDynamicSharedMemorySize, X_SMEM);
    cudaFuncSetAttribute(attn_mma, cudaFuncAttributeMaxDynamicSharedMemorySize, ATTN_SMEM);

    gn_stats<<<dim3(BB * GG, 8), 256>>>(x);
    wconv_kernel<<<512, 256>>>(qkv_w, wq16, 3 * CC * CC);
    wconv_kernel<<<256, 256>>>(proj_w, wp16, CC * CC);
    gn_apply<<<dim3(BB * GG, 8), 256>>>(x, gn_w, gn_b);
    qkv_mma<<<dim3(PP / 256, 24, BB), 256, X_SMEM>>>();
    attn_mma<<<dim3(PP / 128, NBH), 256, ATTN_SMEM>>>();
    proj_mma<<<dim3(PP / 256, CC / 64, BB), 256, X_SMEM>>>(proj_b, x, out);
}

// round 15
// speedup vs baseline: 12.9953x; 1.1113x over previous
#include <cuda_runtime.h>
#include <cuda_fp16.h>
#include <math.h>
#include <stdint.h>

#define BB 2
#define CC 512
#define PP 4096
#define NBH 16
#define GG 32
#define CPG 16
#define EPSV 1e-5f

__device__ __align__(16) __half g_h16[BB * CC * PP];
__device__ __align__(16) __half g_wq16[3 * CC * CC];
__device__ __align__(16) __half g_wp16[CC * CC];
__device__ __align__(16) __half g_q16[NBH * PP * 64];
__device__ __align__(16) __half g_k16[NBH * PP * 64];
__device__ __align__(16) __half g_v16[NBH * PP * 64];
__device__ __align__(16) __half g_at16[BB * CC * PP];
__device__ float g_part[64 * 8 * 2];

__device__ __forceinline__ uint32_t smem_u32(const void* p) {
    uint32_t a;
    asm("{ .reg .u64 t; cvta.to.shared.u64 t, %1; cvt.u32.u64 %0, t; }" : "=r"(a) : "l"(p));
    return a;
}
__device__ __forceinline__ void cpa16(uint32_t dst, const void* src) {
    asm volatile("cp.async.cg.shared.global [%0], [%1], 16;" :: "r"(dst), "l"(src));
}
#define CPA_COMMIT() asm volatile("cp.async.commit_group;" ::: "memory")
#define CPA_WAIT1()  asm volatile("cp.async.wait_group 1;" ::: "memory")
#define CPA_WAIT0()  asm volatile("cp.async.wait_group 0;" ::: "memory")
__device__ __forceinline__ uint32_t cvt2h(float a, float b) {
    uint32_t r;
    asm("cvt.rn.f16x2.f32 %0, %1, %2;" : "=r"(r) : "f"(b), "f"(a));
    return r;
}
__device__ __forceinline__ void ldsm4(uint32_t* r, uint32_t a) {
    asm volatile("ldmatrix.sync.aligned.m8n8.x4.shared.b16 {%0,%1,%2,%3}, [%4];"
        : "=r"(r[0]), "=r"(r[1]), "=r"(r[2]), "=r"(r[3]) : "r"(a));
}
__device__ __forceinline__ void ldsm4t(uint32_t* r, uint32_t a) {
    asm volatile("ldmatrix.sync.aligned.m8n8.x4.trans.shared.b16 {%0,%1,%2,%3}, [%4];"
        : "=r"(r[0]), "=r"(r[1]), "=r"(r[2]), "=r"(r[3]) : "r"(a));
}
__device__ __forceinline__ void mma16816h(float* c, const uint32_t* a, uint32_t b0, uint32_t b1) {
    asm volatile("mma.sync.aligned.m16n8k16.row.col.f32.f16.f16.f32 "
        "{%0,%1,%2,%3}, {%4,%5,%6,%7}, {%8,%9}, {%0,%1,%2,%3};"
        : "+f"(c[0]), "+f"(c[1]), "+f"(c[2]), "+f"(c[3])
        : "r"(a[0]), "r"(a[1]), "r"(a[2]), "r"(a[3]), "r"(b0), "r"(b1));
}

#define LOG2E 1.44269504088896f

// --------- GroupNorm phase 1: partial sums ----------------------------------
__global__ __launch_bounds__(256) void gn_stats(const float* __restrict__ x) {
    int bg = blockIdx.x, sl = blockIdx.y;
    int b = bg / GG, g = bg % GG;
    const float4* xp = (const float4*)(x + ((size_t)b * CC + g * CPG) * PP) + sl * 2048;
    float s = 0.f, s2 = 0.f;
    for (int i = threadIdx.x; i < 2048; i += 256) {
        float4 v = xp[i];
        s += v.x + v.y + v.z + v.w;
        s2 += v.x * v.x + v.y * v.y + v.z * v.z + v.w * v.w;
    }
    __shared__ float rs[256], rs2[256];
    rs[threadIdx.x] = s; rs2[threadIdx.x] = s2;
    __syncthreads();
    for (int o = 128; o > 0; o >>= 1) {
        if (threadIdx.x < o) { rs[threadIdx.x] += rs[threadIdx.x + o]; rs2[threadIdx.x] += rs2[threadIdx.x + o]; }
        __syncthreads();
    }
    if (threadIdx.x == 0) {
        g_part[(bg * 8 + sl) * 2] = rs[0];
        g_part[(bg * 8 + sl) * 2 + 1] = rs2[0];
    }
}

// --------- GroupNorm phase 2: apply -> fp16 ---------------------------------
__global__ __launch_bounds__(256) void gn_apply(const float* __restrict__ x,
        const float* __restrict__ gw, const float* __restrict__ gb) {
    int bg = blockIdx.x, sl = blockIdx.y;
    int b = bg / GG, g = bg % GG;
    float s = 0.f, s2 = 0.f;
#pragma unroll
    for (int i = 0; i < 8; i++) {
        s += g_part[(bg * 8 + i) * 2];
        s2 += g_part[(bg * 8 + i) * 2 + 1];
    }
    float mean = s / (float)(CPG * PP);
    float rstd = rsqrtf(s2 / (float)(CPG * PP) - mean * mean + EPSV);
    size_t base = ((size_t)b * CC + g * CPG) * PP;
    const float4* xp = (const float4*)(x + base);
    for (int ii = threadIdx.x; ii < 2048; ii += 256) {
        int i = sl * 2048 + ii;
        int c = g * CPG + (i >> 10);
        float ga = gw[c] * rstd, be = gb[c];
        float4 v = xp[i];
        uint2 hh;
        hh.x = cvt2h((v.x - mean) * ga + be, (v.y - mean) * ga + be);
        hh.y = cvt2h((v.z - mean) * ga + be, (v.w - mean) * ga + be);
        *(uint2*)(g_h16 + base + (size_t)i * 4) = hh;
    }
}

// --------- convert weights fp32 -> fp16 -------------------------------------
__global__ __launch_bounds__(256) void wconv_kernel(const float* __restrict__ w,
        __half* __restrict__ dh, int n) {
    for (int i = blockIdx.x * 256 + threadIdx.x; i < n; i += gridDim.x * 256) {
        dh[i] = __float2half_rn(w[i]);
    }
}

// --------- raw-mma GEMM core: 8 warps (2 o x 4 p), CTA 64o x 256p -----------
#define XSTG 11520
#define XW_H 3072
#define X_SMEM 36864

__device__ __forceinline__ void gemm_core(uint32_t sb, const __half* W, const __half* H,
        int p0, int tid, float C[2][8][4], int lane, int wo, int wp) {
    auto stage = [&](int buf, int k0) {
        uint32_t bs = sb + buf * XSTG;
        for (int idx = tid; idx < 128; idx += 256) {
            int r = idx >> 1, c = idx & 1;
            cpa16(bs + r * 48 + c * 16, W + (size_t)r * CC + k0 + c * 8);
        }
        for (int idx = tid; idx < 512; idx += 256) {
            int r = idx >> 5, c = idx & 31;
            cpa16(bs + XW_H + r * 528 + c * 16, H + (size_t)(k0 + r) * PP + p0 + c * 8);
        }
    };
    uint32_t lrow = (lane & 7) + ((lane >> 3) & 1) * 8;
    uint32_t lc16 = (uint32_t)(lane >> 4) * 16;

    stage(0, 0);
    CPA_COMMIT();
    for (int kc = 0; kc < 32; kc++) {
        __syncthreads();
        if (kc + 1 < 32) { stage((kc + 1) & 1, (kc + 1) * 16); CPA_COMMIT(); CPA_WAIT1(); }
        else CPA_WAIT0();
        __syncthreads();
        uint32_t bs = sb + (kc & 1) * XSTG;
        uint32_t A[2][4];
#pragma unroll
        for (int mt = 0; mt < 2; mt++)
            ldsm4(A[mt], bs + (uint32_t)(wo * 32 + mt * 16 + lrow) * 48 + lc16);
#pragma unroll
        for (int pt = 0; pt < 4; pt++) {
            uint32_t B4[4];
            ldsm4t(B4, bs + XW_H + lrow * 528 + (uint32_t)wp * 128 + pt * 32 + lc16);
#pragma unroll
            for (int mt = 0; mt < 2; mt++) {
                mma16816h(C[mt][2 * pt], A[mt], B4[0], B4[1]);
                mma16816h(C[mt][2 * pt + 1], A[mt], B4[2], B4[3]);
            }
        }
    }
}

// --------- QKV GEMM + fused transpose epilogue ------------------------------
__global__ __launch_bounds__(256) void qkv_mma() {
    extern __shared__ char sm[];
    uint32_t sb = smem_u32(sm);
    int tid = threadIdx.x, w = tid >> 5, lane = tid & 31;
    int p0 = blockIdx.x << 8;
    int nh = blockIdx.y / 3, part = blockIdx.y % 3;
    int o0 = blockIdx.y << 6;
    int b = blockIdx.z, bh = b * 8 + nh;
    int wo = w >> 2, wp = w & 3;

    float C[2][8][4];
#pragma unroll
    for (int i = 0; i < 2; i++)
#pragma unroll
        for (int j = 0; j < 8; j++)
#pragma unroll
            for (int k = 0; k < 4; k++) C[i][j][k] = 0.f;

    gemm_core(sb, g_wq16 + (size_t)o0 * CC, g_h16 + (size_t)b * CC * PP, p0, tid, C, lane, wo, wp);

    float scale = (part == 0) ? 0.125f * LOG2E : 1.0f;
    __syncthreads();
    __half* Sp = (__half*)sm;
    int r = lane >> 2, cb = 2 * (lane & 3);
#pragma unroll
    for (int mt = 0; mt < 2; mt++) {
        int ol = wo * 32 + mt * 16 + r;
#pragma unroll
        for (int n8 = 0; n8 < 8; n8++) {
            int p = wp * 64 + n8 * 8 + cb;
            Sp[(p + 0) * 72 + ol] = __float2half_rn(C[mt][n8][0] * scale);
            Sp[(p + 1) * 72 + ol] = __float2half_rn(C[mt][n8][1] * scale);
            Sp[(p + 0) * 72 + ol + 8] = __float2half_rn(C[mt][n8][2] * scale);
            Sp[(p + 1) * 72 + ol + 8] = __float2half_rn(C[mt][n8][3] * scale);
        }
    }
    __syncthreads();
    __half* dh = (part == 0 ? g_q16 : part == 1 ? g_k16 : g_v16) + (size_t)bh * PP * 64;
    for (int idx = tid; idx < 2048; idx += 256) {
        int p = idx >> 3, c = idx & 7;
        *(uint4*)(dh + (size_t)(p0 + p) * 64 + c * 8) = *(uint4*)((char*)sm + p * 144 + c * 16);
    }
}

// --------- proj GEMM + bias + residual --------------------------------------
__global__ __launch_bounds__(256) void proj_mma(const float* __restrict__ bias,
        const float* __restrict__ xin, float* __restrict__ out) {
    extern __shared__ char sm[];
    uint32_t sb = smem_u32(sm);
    int tid = threadIdx.x, w = tid >> 5, lane = tid & 31;
    int p0 = blockIdx.x << 8;
    int o0 = blockIdx.y << 6;
    int b = blockIdx.z;
    int wo = w >> 2, wp = w & 3;

    float C[2][8][4];
#pragma unroll
    for (int i = 0; i < 2; i++)
#pragma unroll
        for (int j = 0; j < 8; j++)
#pragma unroll
            for (int k = 0; k < 4; k++) C[i][j][k] = 0.f;

    gemm_core(sb, g_wp16 + (size_t)o0 * CC, g_at16 + (size_t)b * CC * PP, p0, tid, C, lane, wo, wp);

    int r = lane >> 2, cb = 2 * (lane & 3);
#pragma unroll
    for (int mt = 0; mt < 2; mt++) {
        int o = o0 + wo * 32 + mt * 16 + r;
        float bv0 = bias[o], bv1 = bias[o + 8];
#pragma unroll
        for (int n8 = 0; n8 < 8; n8++) {
            int p = p0 + wp * 64 + n8 * 8 + cb;
            size_t off0 = ((size_t)b * CC + o) * PP + p;
            size_t off1 = ((size_t)b * CC + o + 8) * PP + p;
            float2 r0 = *(const float2*)(xin + off0);
            float2 r1 = *(const float2*)(xin + off1);
            *(float2*)(out + off0) = make_float2(C[mt][n8][0] + bv0 + r0.x, C[mt][n8][1] + bv0 + r0.y);
            *(float2*)(out + off1) = make_float2(C[mt][n8][2] + bv1 + r1.x, C[mt][n8][3] + bv1 + r1.y);
        }
    }
}

// --------- attention: 128-thread CTAs, 64 q-rows, 4 CTAs/SM -----------------
// smem: KV double buffer (K 64x144 = 9216 | V +9216), stage 18432 | Ls 36864
#define AKVB 18432
#define ALS  36864
#define ATTN_SMEM 37376

__device__ __forceinline__ void load_kv1(uint32_t base,
        const __half* k16, const __half* v16, int j0, int tid) {
    for (int idx = tid; idx < 1024; idx += 128) {
        int m = idx >> 9, r = (idx >> 3) & 63, c8 = idx & 7;
        uint32_t d = base + m * 9216 + r * 144 + c8 * 16;
        const __half* s = (m ? v16 : k16) + (size_t)(j0 + r) * 64 + c8 * 8;
        cpa16(d, s);
    }
}

__global__ __launch_bounds__(128, 4) void attn_mma() {
    extern __shared__ char sm[];
    uint32_t sb = smem_u32(sm);
    int tid = threadIdx.x, w = tid >> 5, lane = tid & 31;
    int bh = blockIdx.y, b = bh >> 3, nh = bh & 7;
    int i0 = blockIdx.x << 6;  // 64 q rows

    const __half* q16 = g_q16 + ((size_t)bh * PP + i0) * 64;
    const __half* k16 = g_k16 + (size_t)bh * PP * 64;
    const __half* v16 = g_v16 + (size_t)bh * PP * 64;

    uint32_t lrow = (lane & 7) + ((lane >> 3) & 1) * 8;
    uint32_t lc16 = (uint32_t)(lane >> 4) * 16;
    uint32_t qrow = (uint32_t)(w * 16 + lrow) * 144 + lc16;

    // stage Q (64 rows) into buffer0, hoist fragments
    for (int idx = tid; idx < 512; idx += 128) {
        int r = idx >> 3, c8 = idx & 7;
        cpa16(sb + r * 144 + c8 * 16, q16 + (size_t)r * 64 + c8 * 8);
    }
    CPA_COMMIT(); CPA_WAIT0();
    __syncthreads();
    uint32_t Qf[4][4];
#pragma unroll
    for (int s = 0; s < 4; s++) ldsm4(Qf[s], sb + qrow + s * 32);
    __syncthreads();

    load_kv1(sb, k16, v16, 0, tid);
    CPA_COMMIT();

    float O[8][4];
#pragma unroll
    for (int i = 0; i < 8; i++)
#pragma unroll
        for (int j = 0; j < 4; j++) O[i][j] = 0.f;
    float lsum0 = 0.f, lsum1 = 0.f;

    for (int t = 0; t < 64; t++) {
        __syncthreads();
        if (t + 1 < 64) {
            load_kv1(sb + ((t + 1) & 1) * AKVB, k16, v16, (t + 1) * 64, tid);
            CPA_COMMIT(); CPA_WAIT1();
        } else CPA_WAIT0();
        __syncthreads();
        uint32_t kb = sb + (t & 1) * AKVB;

        // ---- S = QK^T ----
        float S[8][4];
#pragma unroll
        for (int i = 0; i < 8; i++)
#pragma unroll
            for (int j = 0; j < 4; j++) S[i][j] = 0.f;
#pragma unroll
        for (int s = 0; s < 4; s++) {
            uint32_t k4[4];
#pragma unroll
            for (int g = 0; g < 4; g++) {
                ldsm4(k4, kb + (uint32_t)(g * 16 + lrow) * 144 + s * 32 + lc16);
                mma16816h(S[2 * g], Qf[s], k4[0], k4[2]);
                mma16816h(S[2 * g + 1], Qf[s], k4[1], k4[3]);
            }
        }
        // ---- exp2 (f16x2; S pre-scaled by log2e upstream) ----
        uint32_t Ph[4][4];
        __half2 sum0 = __float2half2_rn(0.f), sum1 = __float2half2_rn(0.f);
#pragma unroll
        for (int t8 = 0; t8 < 8; t8++) {
            __half2 x01 = __floats2half2_rn(S[t8][0], S[t8][1]);
            __half2 x23 = __floats2half2_rn(S[t8][2], S[t8][3]);
            __half2 e01 = h2exp2(x01);
            __half2 e23 = h2exp2(x23);
            int s = t8 >> 1, o = (t8 & 1) * 2;
            Ph[s][o] = *(uint32_t*)&e01;
            Ph[s][o + 1] = *(uint32_t*)&e23;
            sum0 = __hadd2(sum0, e01);
            sum1 = __hadd2(sum1, e23);
        }
        lsum0 += __low2float(sum0) + __high2float(sum0);
        lsum1 += __low2float(sum1) + __high2float(sum1);
        // ---- O += P V ----
#pragma unroll
        for (int s = 0; s < 4; s++) {
            uint32_t v4[4];
#pragma unroll
            for (int g = 0; g < 4; g++) {
                ldsm4t(v4, kb + 9216 + (uint32_t)(s * 16 + lrow) * 144 + g * 32 + lc16);
                mma16816h(O[2 * g], Ph[s], v4[0], v4[1]);
                mma16816h(O[2 * g + 1], Ph[s], v4[2], v4[3]);
            }
        }
    }

    float* Ls = (float*)(sm + ALS);
    lsum0 += __shfl_xor_sync(0xffffffffu, lsum0, 1);
    lsum0 += __shfl_xor_sync(0xffffffffu, lsum0, 2);
    lsum1 += __shfl_xor_sync(0xffffffffu, lsum1, 1);
    lsum1 += __shfl_xor_sync(0xffffffffu, lsum1, 2);
    int r0 = w * 16 + (lane >> 2);
    if ((lane & 3) == 0) { Ls[r0] = lsum0; Ls[r0 + 8] = lsum1; }
    __syncthreads();
    float inv0 = 1.f / Ls[r0], inv1 = 1.f / Ls[r0 + 8];
    float* Ss = (float*)sm;  // 64 x 68 f32 = 17408 <= buffer0
    int cb = 2 * (lane & 3);
#pragma unroll
    for (int t8 = 0; t8 < 8; t8++) {
        int c = t8 * 8 + cb;
        Ss[r0 * 68 + c] = O[t8][0] * inv0;
        Ss[r0 * 68 + c + 1] = O[t8][1] * inv0;
        Ss[(r0 + 8) * 68 + c] = O[t8][2] * inv1;
        Ss[(r0 + 8) * 68 + c + 1] = O[t8][3] * inv1;
    }
    __syncthreads();
    __half* ah = g_at16 + ((size_t)b * CC + nh * 64) * PP + i0;
    for (int idx = tid; idx < 1024; idx += 128) {
        int d = idx >> 4, i4 = (idx & 15) << 2;
        uint2 hh;
        hh.x = cvt2h(Ss[(i4 + 0) * 68 + d], Ss[(i4 + 1) * 68 + d]);
        hh.y = cvt2h(Ss[(i4 + 2) * 68 + d], Ss[(i4 + 3) * 68 + d]);
        *(uint2*)(ah + (size_t)d * PP + i4) = hh;
    }
}

// ---------------------------------------------------------------------------
extern "C" void kernel_launch(void* const* d_in, const int* in_sizes, int n_in,
                              void* d_out, int out_size) {
    const float* x = (const float*)d_in[0];
    const float* qkv_w = (const float*)d_in[1];
    const float* proj_w = (const float*)d_in[2];
    const float* proj_b = (const float*)d_in[3];
    const float* gn_w = (const float*)d_in[4];
    const float* gn_b = (const float*)d_in[5];
    float* out = (float*)d_out;

    __half *wq16, *wp16;
    cudaGetSymbolAddress((void**)&wq16, g_wq16);
    cudaGetSymbolAddress((void**)&wp16, g_wp16);

    cudaFuncSetAttribute(qkv_mma, cudaFuncAttributeMaxDynamicSharedMemorySize, X_SMEM);
    cudaFuncSetAttribute(proj_mma, cudaFuncAttributeMaxDynamicSharedMemorySize, X_SMEM);
    cudaFuncSetAttribute(attn_mma, cudaFuncAttributeMaxDynamicSharedMemorySize, ATTN_SMEM);

    gn_stats<<<dim3(BB * GG, 8), 256>>>(x);
    wconv_kernel<<<512, 256>>>(qkv_w, wq16, 3 * CC * CC);
    wconv_kernel<<<256, 256>>>(proj_w, wp16, CC * CC);
    gn_apply<<<dim3(BB * GG, 8), 256>>>(x, gn_w, gn_b);
    qkv_mma<<<dim3(PP / 256, 24, BB), 256, X_SMEM>>>();
    attn_mma<<<dim3(PP / 64, NBH), 128, ATTN_SMEM>>>();
    proj_mma<<<dim3(PP / 256, CC / 64, BB), 256, X_SMEM>>>(proj_b, x, out);
}